// round 9
// baseline (speedup 1.0000x reference)
#include <cuda_runtime.h>
#include <cstdint>

#define U_N   100000
#define I_N   50000
#define R_N   5
#define E_N   100000
#define K_N   4
#define D_N   16
#define RD_N  64
#define OUT_N 64
#define KF_N  2

// ---------------- device scratch ----------------
__device__ float g_norm_u[U_N];
__device__ float g_norm_i[I_N];
__device__ float g_ead[R_N * E_N];
__device__ float g_ufeat[U_N * D_N];
__device__ float g_ifeat[I_N * D_N];
__device__ float g_invn_u[R_N * U_N];
__device__ float g_invn_i[R_N * I_N];
__device__ float g_P_u[(size_t)R_N * U_N * D_N];
__device__ float g_P_i[(size_t)R_N * I_N * D_N];

// ---------------- helpers ----------------
__device__ __forceinline__ float red16(float v) {
    v += __shfl_xor_sync(0xffffffffu, v, 1);
    v += __shfl_xor_sync(0xffffffffu, v, 2);
    v += __shfl_xor_sync(0xffffffffu, v, 4);
    v += __shfl_xor_sync(0xffffffffu, v, 8);
    return v;
}
__device__ __forceinline__ void red_v4(float* addr, float4 v) {
    asm volatile("red.global.add.v4.f32 [%0], {%1, %2, %3, %4};"
                 :: "l"(addr), "f"(v.x), "f"(v.y), "f"(v.z), "f"(v.w)
                 : "memory");
}
__device__ __forceinline__ unsigned long long dup2(float v) {
    unsigned long long d;
    asm("mov.b64 %0, {%1, %1};" : "=l"(d) : "f"(v));
    return d;
}
__device__ __forceinline__ unsigned long long fma2(unsigned long long a,
                                                   unsigned long long b,
                                                   unsigned long long c) {
    unsigned long long d;
    asm("fma.rn.f32x2 %0, %1, %2, %3;" : "=l"(d) : "l"(a), "l"(b), "l"(c));
    return d;
}
__device__ __forceinline__ void unpack2(unsigned long long v, float& lo, float& hi) {
    asm("mov.b64 {%0, %1}, %2;" : "=f"(lo), "=f"(hi) : "l"(v));
}

// ---------------- kernel A: invnorm + node projection + accumulator zeroing ----------------
__global__ __launch_bounds__(256) void precompute_kernel(
    const float* __restrict__ user_h, const float* __restrict__ item_h,
    const float* __restrict__ node_w_fwd, const float* __restrict__ node_w_rev)
{
    __shared__ float sw[256];
    const int r = blockIdx.y;
    const bool isU = (blockIdx.z == 0);
    const float* W = isU ? node_w_fwd : node_w_rev;
    if (threadIdx.x < 256) sw[threadIdx.x] = W[r * 256 + threadIdx.x];
    __syncthreads();

    const int N = isU ? U_N : I_N;
    const int n = blockIdx.x * 256 + threadIdx.x;
    if (n >= N) return;

    if (r == 0) {
        float4 z = {0.f, 0.f, 0.f, 0.f};
        if (isU) {
            g_norm_u[n] = 0.f;
            float4* f = (float4*)(g_ufeat + n * 16);
            f[0] = z; f[1] = z; f[2] = z; f[3] = z;
        } else {
            g_norm_i[n] = 0.f;
            float4* f = (float4*)(g_ifeat + n * 16);
            f[0] = z; f[1] = z; f[2] = z; f[3] = z;
        }
    }

    const float* h = (isU ? user_h : item_h) + ((size_t)r * N + n) * 16;
    float xs[16];
    const float4* h4 = (const float4*)h;
    float4 x0 = h4[0], x1 = h4[1], x2 = h4[2], x3 = h4[3];
    xs[0]=x0.x; xs[1]=x0.y; xs[2]=x0.z; xs[3]=x0.w;
    xs[4]=x1.x; xs[5]=x1.y; xs[6]=x1.z; xs[7]=x1.w;
    xs[8]=x2.x; xs[9]=x2.y; xs[10]=x2.z; xs[11]=x2.w;
    xs[12]=x3.x; xs[13]=x3.y; xs[14]=x3.z; xs[15]=x3.w;

    float ss = 0.f;
#pragma unroll
    for (int j = 0; j < 16; j++) ss = fmaf(xs[j], xs[j], ss);
    float invn = rsqrtf(ss);
    if (isU) g_invn_u[(size_t)r * U_N + n] = invn;
    else     g_invn_i[(size_t)r * I_N + n] = invn;

    float4 a0 = {0,0,0,0}, a1 = {0,0,0,0}, a2 = {0,0,0,0}, a3 = {0,0,0,0};
    const float4* sw4 = (const float4*)sw;
#pragma unroll
    for (int j = 0; j < 16; j++) {
        float xv = xs[j];
        float4 w0 = sw4[j*4+0], w1 = sw4[j*4+1], w2 = sw4[j*4+2], w3 = sw4[j*4+3];
        a0.x = fmaf(xv, w0.x, a0.x); a0.y = fmaf(xv, w0.y, a0.y);
        a0.z = fmaf(xv, w0.z, a0.z); a0.w = fmaf(xv, w0.w, a0.w);
        a1.x = fmaf(xv, w1.x, a1.x); a1.y = fmaf(xv, w1.y, a1.y);
        a1.z = fmaf(xv, w1.z, a1.z); a1.w = fmaf(xv, w1.w, a1.w);
        a2.x = fmaf(xv, w2.x, a2.x); a2.y = fmaf(xv, w2.y, a2.y);
        a2.z = fmaf(xv, w2.z, a2.z); a2.w = fmaf(xv, w2.w, a2.w);
        a3.x = fmaf(xv, w3.x, a3.x); a3.y = fmaf(xv, w3.y, a3.y);
        a3.z = fmaf(xv, w3.z, a3.z); a3.w = fmaf(xv, w3.w, a3.w);
    }
    float4* P = (float4*)((isU ? g_P_u : g_P_i) + ((size_t)r * N + n) * 16);
    P[0] = a0; P[1] = a1; P[2] = a2; P[3] = a3;
}

// ---------------- kernel 1: per-edge ead, 2 edges/warp for MLP ----------------
__global__ __launch_bounds__(256) void phase1_kernel(
    const float* __restrict__ user_h,     const float* __restrict__ item_h,
    const float* __restrict__ user_hsum,  const float* __restrict__ item_hsum,
    const float* __restrict__ review_feat,
    const float* __restrict__ prototypes, const float* __restrict__ eta,
    const int*   __restrict__ rows,       const int*   __restrict__ cols)
{
    __shared__ float sm[256];
    const int r = blockIdx.y;
    if (threadIdx.x < 256) sm[threadIdx.x] = prototypes[threadIdx.x];
    __syncthreads();

    const int lane = threadIdx.x & 31;
    const int warp = threadIdx.x >> 5;
    const int e0 = blockIdx.x * 16 + warp * 2;     // E divisible by 16
    const unsigned FULL = 0xffffffffu;
    const int dh = lane & 15;

    const size_t idx0 = (size_t)r * E_N + e0;
    const size_t idx1 = idx0 + 1;
    const int row0 = __ldg(rows + idx0), row1 = __ldg(rows + idx1);
    const int col0 = __ldg(cols + idx0), col1 = __ldg(cols + idx1);

    // ---- issue all loads for both edges (max MLP) ----
    float hval0, hval1;
    float4 hs0, hs1;
    if (lane < 16) {
        hval0 = __ldg(user_h + ((size_t)r * U_N + row0) * 16 + dh);
        hval1 = __ldg(user_h + ((size_t)r * U_N + row1) * 16 + dh);
        hs0 = *(const float4*)(user_hsum + ((size_t)r * U_N + row0) * 64 + 4 * lane);
        hs1 = *(const float4*)(user_hsum + ((size_t)r * U_N + row1) * 64 + 4 * lane);
    } else {
        hval0 = __ldg(item_h + ((size_t)r * I_N + col0) * 16 + dh);
        hval1 = __ldg(item_h + ((size_t)r * I_N + col1) * 16 + dh);
        hs0 = *(const float4*)(item_hsum + ((size_t)r * I_N + col0) * 64 + 4 * (lane - 16));
        hs1 = *(const float4*)(item_hsum + ((size_t)r * I_N + col1) * 64 + 4 * (lane - 16));
    }
    const float4* rf40 = (const float4*)(review_feat + idx0 * 256);
    const float4* rf41 = (const float4*)(review_feat + idx1 * 256);
    float4 ra0 = __ldcs(rf40 + lane * 2), rb0 = __ldcs(rf40 + lane * 2 + 1);
    float4 ra1 = __ldcs(rf41 + lane * 2), rb1 = __ldcs(rf41 + lane * 2 + 1);

    const float invnu0 = __ldg(g_invn_u + (size_t)r * U_N + row0);
    const float invnu1 = __ldg(g_invn_u + (size_t)r * U_N + row1);
    const float invni0 = __ldg(g_invn_i + (size_t)r * I_N + col0);
    const float invni1 = __ldg(g_invn_i + (size_t)r * I_N + col1);
    const float etav0 = __ldg(eta + idx0);
    const float etav1 = __ldg(eta + idx1);

    const float4* pr4 = (const float4*)sm;
    const float4 pa = pr4[lane * 2];
    const float4 pb = pr4[lane * 2 + 1];

    // ---- edge 0 ----
    float oth = __shfl_xor_sync(FULL, hval0, 16);
    float dot = red16(hval0 * oth);
    float sim_k0 = 2.0f * dot * invnu0 * invni0;
    float4 o4;
    o4.x = __shfl_xor_sync(FULL, hs0.x, 16);
    o4.y = __shfl_xor_sync(FULL, hs0.y, 16);
    o4.z = __shfl_xor_sync(FULL, hs0.z, 16);
    o4.w = __shfl_xor_sync(FULL, hs0.w, 16);
    float p = hs0.x * o4.x + hs0.y * o4.y + hs0.z * o4.z + hs0.w * o4.w;
    p += __shfl_xor_sync(FULL, p, 1);
    p += __shfl_xor_sync(FULL, p, 2);
    float ek = __expf(2.0f * p);
    float Ssim0 = ek;
    Ssim0 += __shfl_xor_sync(FULL, Ssim0, 4);
    Ssim0 += __shfl_xor_sync(FULL, Ssim0, 8);
    float exp_sim0 = __expf(sim_k0) / Ssim0;

    float ad = ra0.x * pa.x + ra0.y * pa.y + ra0.z * pa.z + ra0.w * pa.w
             + rb0.x * pb.x + rb0.y * pb.y + rb0.z * pb.z + rb0.w * pb.w;
    ad += __shfl_xor_sync(FULL, ad, 1);
    ad += __shfl_xor_sync(FULL, ad, 2);
    ad += __shfl_xor_sync(FULL, ad, 4);
    float eab = __expf(2.0f * ad);
    float Sad0 = eab;
    Sad0 += __shfl_xor_sync(FULL, Sad0, 8);
    Sad0 += __shfl_xor_sync(FULL, Sad0, 16);
    float e2_0 = __shfl_sync(FULL, eab, 16);
    float g0 = 1.0f / (1.0f + __expf(-etav0));
    float ead0 = g0 * (e2_0 / Sad0) + (1.0f - g0) * exp_sim0;

    // ---- edge 1 ----
    oth = __shfl_xor_sync(FULL, hval1, 16);
    dot = red16(hval1 * oth);
    float sim_k1 = 2.0f * dot * invnu1 * invni1;
    o4.x = __shfl_xor_sync(FULL, hs1.x, 16);
    o4.y = __shfl_xor_sync(FULL, hs1.y, 16);
    o4.z = __shfl_xor_sync(FULL, hs1.z, 16);
    o4.w = __shfl_xor_sync(FULL, hs1.w, 16);
    p = hs1.x * o4.x + hs1.y * o4.y + hs1.z * o4.z + hs1.w * o4.w;
    p += __shfl_xor_sync(FULL, p, 1);
    p += __shfl_xor_sync(FULL, p, 2);
    ek = __expf(2.0f * p);
    float Ssim1 = ek;
    Ssim1 += __shfl_xor_sync(FULL, Ssim1, 4);
    Ssim1 += __shfl_xor_sync(FULL, Ssim1, 8);
    float exp_sim1 = __expf(sim_k1) / Ssim1;

    ad = ra1.x * pa.x + ra1.y * pa.y + ra1.z * pa.z + ra1.w * pa.w
       + rb1.x * pb.x + rb1.y * pb.y + rb1.z * pb.z + rb1.w * pb.w;
    ad += __shfl_xor_sync(FULL, ad, 1);
    ad += __shfl_xor_sync(FULL, ad, 2);
    ad += __shfl_xor_sync(FULL, ad, 4);
    eab = __expf(2.0f * ad);
    float Sad1 = eab;
    Sad1 += __shfl_xor_sync(FULL, Sad1, 8);
    Sad1 += __shfl_xor_sync(FULL, Sad1, 16);
    float e2_1 = __shfl_sync(FULL, eab, 16);
    float g1 = 1.0f / (1.0f + __expf(-etav1));
    float ead1 = g1 * (e2_1 / Sad1) + (1.0f - g1) * exp_sim1;

    // lane 0 commits edge 0, lane 1 commits edge 1 (both values warp-uniform)
    if (lane == 0) {
        g_ead[idx0] = ead0;
        atomicAdd(&g_norm_u[row0], ead0);
        atomicAdd(&g_norm_i[col0], ead0);
    } else if (lane == 1) {
        g_ead[idx1] = ead1;
        atomicAdd(&g_norm_u[row1], ead1);
        atomicAdd(&g_norm_i[col1], ead1);
    }
}

// ---------------- fused kernel: review projection + weight + scatter ----------------
__global__ __launch_bounds__(256) void proj_scatter_kernel(
    const float* __restrict__ review_feat,
    const float* __restrict__ review_w_fwd, const float* __restrict__ review_w_rev,
    const int* __restrict__ rows, const int* __restrict__ cols,
    float* __restrict__ int_dist_out)
{
    __shared__ float      smWT[32 * 68];
    __shared__ ulonglong2 smrf[32 * 33];
    __shared__ float      smres[64 * 33];
    const int r = blockIdx.y;
    const int tid = threadIdx.x;

    for (int i = tid; i < 2048; i += 256) {
        int o = i & 31, j = i >> 5;
        float w = (o < 16) ? review_w_fwd[r * 1024 + j * 16 + o]
                           : review_w_rev[r * 1024 + j * 16 + (o - 16)];
        smWT[o * 68 + j] = w;
    }

    const int e0 = blockIdx.x * 64;
    float* smrf_f = (float*)smrf;
    for (int i = tid; i < 1024; i += 256) {
        int e = i >> 4, q = i & 15;
        int eg = e0 + e;
        float4 v = {0,0,0,0};
        if (eg < E_N)
            v = __ldcs((const float4*)(review_feat + ((size_t)r * E_N + eg) * 256 + 128) + q);
        int p = e >> 1, h = e & 1;
        int jf = q * 4;
        int base = (p * 33 + (jf >> 1)) * 4 + h;
        smrf_f[base + 0] = v.x;
        smrf_f[base + 2] = v.y;
        smrf_f[base + 4] = v.z;
        smrf_f[base + 6] = v.w;
    }
    __syncthreads();

    {
        const int lane = tid & 31;
        const int warp = tid >> 5;
        const int pbase = warp * 4;
        unsigned long long acc2[4] = {0ull, 0ull, 0ull, 0ull};
        const float4* wt4 = (const float4*)(smWT + lane * 68);
#pragma unroll
        for (int jq = 0; jq < 16; jq++) {
            float4 wv = wt4[jq];
            unsigned long long w0 = dup2(wv.x), w1 = dup2(wv.y);
            unsigned long long w2 = dup2(wv.z), w3 = dup2(wv.w);
#pragma unroll
            for (int pp = 0; pp < 4; pp++) {
                const ulonglong2* rp = smrf + (pbase + pp) * 33 + jq * 2;
                ulonglong2 rva = rp[0];
                ulonglong2 rvb = rp[1];
                acc2[pp] = fma2(rva.x, w0, acc2[pp]);
                acc2[pp] = fma2(rva.y, w1, acc2[pp]);
                acc2[pp] = fma2(rvb.x, w2, acc2[pp]);
                acc2[pp] = fma2(rvb.y, w3, acc2[pp]);
            }
        }
#pragma unroll
        for (int pp = 0; pp < 4; pp++) {
            float lo, hi;
            unpack2(acc2[pp], lo, hi);
            int el = warp * 8 + 2 * pp;
            smres[el * 33 + lane] = lo;
            smres[(el + 1) * 33 + lane] = hi;
        }
    }
    __syncthreads();

#pragma unroll
    for (int it = 0; it < 2; it++) {
        int item = tid + it * 256;
        int el = item >> 3;
        int q  = item & 7;
        int eg = e0 + el;
        if (eg >= E_N) continue;
        const size_t idx = (size_t)r * E_N + eg;
        const int row = rows[idx];
        const int col = cols[idx];
        const float ead = g_ead[idx];
        const float w = ead * rsqrtf(g_norm_u[row] * g_norm_i[col]);
        if (q == 0) int_dist_out[idx] = w;

        float4 p4;
        float* dest;
        const float* res = smres + el * 33;
        float m0, m1, m2, m3;
        if (q < 4) {
            m0 = res[q*4+0]; m1 = res[q*4+1]; m2 = res[q*4+2]; m3 = res[q*4+3];
            p4 = *(const float4*)(g_P_u + ((size_t)r * U_N + row) * 16 + q * 4);
            dest = g_ifeat + col * 16 + q * 4;
        } else {
            const int qq = q - 4;
            m0 = res[16+qq*4+0]; m1 = res[16+qq*4+1]; m2 = res[16+qq*4+2]; m3 = res[16+qq*4+3];
            p4 = *(const float4*)(g_P_i + ((size_t)r * I_N + col) * 16 + qq * 4);
            dest = g_ufeat + row * 16 + qq * 4;
        }
        float4 mv;
        mv.x = (m0 + p4.x) * w;
        mv.y = (m1 + p4.y) * w;
        mv.z = (m2 + p4.z) * w;
        mv.w = (m3 + p4.w) * w;
        red_v4(dest, mv);
    }
}

// ---------------- kernel 3: leaky + FC, float4 outputs ----------------
#define NB_U ((U_N + 63) / 64)
#define NB_I ((I_N + 63) / 64)
__global__ __launch_bounds__(256) void fc_kernel(
    const float* __restrict__ ufc_w, const float* __restrict__ ufc_b,
    const float* __restrict__ ifc_w, const float* __restrict__ ifc_b,
    float* __restrict__ out)
{
    __shared__ float smx[64 * 17];
    const int tid = threadIdx.x;
    const bool isU = (blockIdx.x < NB_U);
    const int nb = (isU ? blockIdx.x : (blockIdx.x - NB_U)) * 64;
    const int N = isU ? U_N : I_N;
    const float* feat = isU ? g_ufeat : g_ifeat;
    const float* W = isU ? ufc_w : ifc_w;
    const float* B = isU ? ufc_b : ifc_b;
    float* outp = out + (isU ? 0 : (size_t)U_N * 64);

    for (int i = tid; i < 1024; i += 256) {
        int n = i >> 4, j = i & 15;
        int ng = nb + n;
        float x = (ng < N) ? feat[ng * 16 + j] : 0.f;
        x = (x >= 0.f) ? x : 0.1f * x;
        smx[n * 17 + j] = x;
    }
    __syncthreads();

    const int og = tid & 15;          // output group: 4 outs at og*4
    const int gn = tid >> 4;          // node group: nodes gn, gn+16, gn+32, gn+48
    float4 wr4[16];
#pragma unroll
    for (int j = 0; j < 16; j++)
        wr4[j] = *(const float4*)(W + j * 64 + og * 4);
    const float4 b4 = *(const float4*)(B + og * 4);

#pragma unroll
    for (int i = 0; i < 4; i++) {
        int n = gn + i * 16;
        int ng = nb + n;
        if (ng < N) {
            float4 acc = b4;
            const float* xr = smx + n * 17;
#pragma unroll
            for (int j = 0; j < 16; j++) {
                float xv = xr[j];
                acc.x = fmaf(xv, wr4[j].x, acc.x);
                acc.y = fmaf(xv, wr4[j].y, acc.y);
                acc.z = fmaf(xv, wr4[j].z, acc.z);
                acc.w = fmaf(xv, wr4[j].w, acc.w);
            }
            *(float4*)(outp + (size_t)ng * 64 + og * 4) = acc;
        }
    }
}

// ---------------- launch ----------------
extern "C" void kernel_launch(void* const* d_in, const int* in_sizes, int n_in,
                              void* d_out, int out_size)
{
    const float* user_h       = (const float*)d_in[0];
    const float* item_h       = (const float*)d_in[1];
    const float* user_hsum    = (const float*)d_in[2];
    const float* item_hsum    = (const float*)d_in[3];
    const float* review_feat  = (const float*)d_in[4];
    const float* prototypes   = (const float*)d_in[5];
    const float* eta          = (const float*)d_in[6];
    const float* node_w_fwd   = (const float*)d_in[7];
    const float* node_w_rev   = (const float*)d_in[8];
    const float* review_w_fwd = (const float*)d_in[9];
    const float* review_w_rev = (const float*)d_in[10];
    const float* ufc_w        = (const float*)d_in[11];
    const float* ufc_b        = (const float*)d_in[12];
    const float* ifc_w        = (const float*)d_in[13];
    const float* ifc_b        = (const float*)d_in[14];
    const int*   rows         = (const int*)d_in[15];
    const int*   cols         = (const int*)d_in[16];
    float* out = (float*)d_out;

    dim3 pgrid((U_N + 255) / 256, R_N, 2);
    precompute_kernel<<<pgrid, 256>>>(user_h, item_h, node_w_fwd, node_w_rev);

    dim3 egrid(E_N / 16, R_N);
    phase1_kernel<<<egrid, 256>>>(user_h, item_h, user_hsum, item_hsum,
                                  review_feat, prototypes, eta, rows, cols);

    dim3 bgrid((E_N + 63) / 64, R_N);
    proj_scatter_kernel<<<bgrid, 256>>>(review_feat, review_w_fwd, review_w_rev,
                                        rows, cols,
                                        out + (size_t)(U_N + I_N) * OUT_N);

    fc_kernel<<<NB_U + NB_I, 256>>>(ufc_w, ufc_b, ifc_w, ifc_b, out);
}

// round 10
// speedup vs baseline: 1.1040x; 1.1040x over previous
#include <cuda_runtime.h>
#include <cstdint>

#define U_N   100000
#define I_N   50000
#define R_N   5
#define E_N   100000
#define K_N   4
#define D_N   16
#define RD_N  64
#define OUT_N 64
#define KF_N  2

// ---------------- device scratch ----------------
__device__ float g_norm_u[U_N];
__device__ float g_norm_i[I_N];
__device__ float g_ead[R_N * E_N];
__device__ float g_ufeat[U_N * D_N];
__device__ float g_ifeat[I_N * D_N];
__device__ float g_P_u[(size_t)R_N * U_N * D_N];
__device__ float g_P_i[(size_t)R_N * I_N * D_N];

// ---------------- helpers ----------------
__device__ __forceinline__ float red16(float v) {
    v += __shfl_xor_sync(0xffffffffu, v, 1);
    v += __shfl_xor_sync(0xffffffffu, v, 2);
    v += __shfl_xor_sync(0xffffffffu, v, 4);
    v += __shfl_xor_sync(0xffffffffu, v, 8);
    return v;
}
__device__ __forceinline__ void red_v4(float* addr, float4 v) {
    asm volatile("red.global.add.v4.f32 [%0], {%1, %2, %3, %4};"
                 :: "l"(addr), "f"(v.x), "f"(v.y), "f"(v.z), "f"(v.w)
                 : "memory");
}
__device__ __forceinline__ unsigned long long dup2(float v) {
    unsigned long long d;
    asm("mov.b64 %0, {%1, %1};" : "=l"(d) : "f"(v));
    return d;
}
__device__ __forceinline__ unsigned long long fma2(unsigned long long a,
                                                   unsigned long long b,
                                                   unsigned long long c) {
    unsigned long long d;
    asm("fma.rn.f32x2 %0, %1, %2, %3;" : "=l"(d) : "l"(a), "l"(b), "l"(c));
    return d;
}
__device__ __forceinline__ void unpack2(unsigned long long v, float& lo, float& hi) {
    asm("mov.b64 {%0, %1}, %2;" : "=f"(lo), "=f"(hi) : "l"(v));
}

// ---------------- kernel 0: zero accumulators (main stream, before phase1) ----------------
__global__ void zero_kernel() {
    int idx = blockIdx.x * 256 + threadIdx.x;
    if (idx < U_N)        g_norm_u[idx] = 0.f;
    if (idx < I_N)        g_norm_i[idx] = 0.f;
    if (idx < U_N * D_N)  g_ufeat[idx]  = 0.f;
    if (idx < I_N * D_N)  g_ifeat[idx]  = 0.f;
}

// ---------------- kernel A: node projection only (side stream, overlaps phase1) ----------------
__global__ __launch_bounds__(256) void precompute_kernel(
    const float* __restrict__ user_h, const float* __restrict__ item_h,
    const float* __restrict__ node_w_fwd, const float* __restrict__ node_w_rev)
{
    __shared__ float sw[256];
    const int r = blockIdx.y;
    const bool isU = (blockIdx.z == 0);
    const float* W = isU ? node_w_fwd : node_w_rev;
    if (threadIdx.x < 256) sw[threadIdx.x] = W[r * 256 + threadIdx.x];
    __syncthreads();

    const int N = isU ? U_N : I_N;
    const int n = blockIdx.x * 256 + threadIdx.x;
    if (n >= N) return;

    const float* h = (isU ? user_h : item_h) + ((size_t)r * N + n) * 16;
    float xs[16];
    const float4* h4 = (const float4*)h;
    float4 x0 = h4[0], x1 = h4[1], x2 = h4[2], x3 = h4[3];
    xs[0]=x0.x; xs[1]=x0.y; xs[2]=x0.z; xs[3]=x0.w;
    xs[4]=x1.x; xs[5]=x1.y; xs[6]=x1.z; xs[7]=x1.w;
    xs[8]=x2.x; xs[9]=x2.y; xs[10]=x2.z; xs[11]=x2.w;
    xs[12]=x3.x; xs[13]=x3.y; xs[14]=x3.z; xs[15]=x3.w;

    float4 a0 = {0,0,0,0}, a1 = {0,0,0,0}, a2 = {0,0,0,0}, a3 = {0,0,0,0};
    const float4* sw4 = (const float4*)sw;
#pragma unroll
    for (int j = 0; j < 16; j++) {
        float xv = xs[j];
        float4 w0 = sw4[j*4+0], w1 = sw4[j*4+1], w2 = sw4[j*4+2], w3 = sw4[j*4+3];
        a0.x = fmaf(xv, w0.x, a0.x); a0.y = fmaf(xv, w0.y, a0.y);
        a0.z = fmaf(xv, w0.z, a0.z); a0.w = fmaf(xv, w0.w, a0.w);
        a1.x = fmaf(xv, w1.x, a1.x); a1.y = fmaf(xv, w1.y, a1.y);
        a1.z = fmaf(xv, w1.z, a1.z); a1.w = fmaf(xv, w1.w, a1.w);
        a2.x = fmaf(xv, w2.x, a2.x); a2.y = fmaf(xv, w2.y, a2.y);
        a2.z = fmaf(xv, w2.z, a2.z); a2.w = fmaf(xv, w2.w, a2.w);
        a3.x = fmaf(xv, w3.x, a3.x); a3.y = fmaf(xv, w3.y, a3.y);
        a3.z = fmaf(xv, w3.z, a3.z); a3.w = fmaf(xv, w3.w, a3.w);
    }
    float4* P = (float4*)((isU ? g_P_u : g_P_i) + ((size_t)r * N + n) * 16);
    P[0] = a0; P[1] = a1; P[2] = a2; P[3] = a3;
}

// ---------------- kernel 1: per-edge ead (R8 structure + inline invnorm) ----------------
__global__ __launch_bounds__(256) void phase1_kernel(
    const float* __restrict__ user_h,     const float* __restrict__ item_h,
    const float* __restrict__ user_hsum,  const float* __restrict__ item_hsum,
    const float* __restrict__ review_feat,
    const float* __restrict__ prototypes, const float* __restrict__ eta,
    const int*   __restrict__ rows,       const int*   __restrict__ cols)
{
    __shared__ float sm[256];
    const int r = blockIdx.y;
    if (threadIdx.x < 256) sm[threadIdx.x] = prototypes[threadIdx.x];
    __syncthreads();

    const int lane = threadIdx.x & 31;
    const int warp = threadIdx.x >> 5;
    const int e = blockIdx.x * 8 + warp;
    if (e >= E_N) return;

    const size_t idx = (size_t)r * E_N + e;
    const int row = rows[idx];
    const int col = cols[idx];
    const unsigned FULL = 0xffffffffu;

    const int dh = lane & 15;
    float hval;
    if (lane < 16) hval = __ldg(user_h + ((size_t)r * U_N + row) * 16 + dh);
    else           hval = __ldg(item_h + ((size_t)r * I_N + col) * 16 + dh);

    const float* uh = user_hsum + ((size_t)r * U_N + row) * 64;
    const float* ih = item_hsum + ((size_t)r * I_N + col) * 64;
    float4 hs;
    if (lane < 16) hs = *(const float4*)(uh + 4 * lane);
    else           hs = *(const float4*)(ih + 4 * (lane - 16));

    const float4* rf4 = (const float4*)(review_feat + idx * 256);
    float4 ra = __ldcs(rf4 + lane * 2);
    float4 rb = __ldcs(rf4 + lane * 2 + 1);

    const float etav = eta[idx];

    // sim_k with inline norms: dot over halves + per-half sq-sums
    float othv = __shfl_xor_sync(FULL, hval, 16);
    float dot = red16(hval * othv);
    float ss = red16(hval * hval);
    float oss = __shfl_xor_sync(FULL, ss, 16);
    float sim_k = 2.0f * dot * rsqrtf(ss * oss);

    float4 o4;
    o4.x = __shfl_xor_sync(FULL, hs.x, 16);
    o4.y = __shfl_xor_sync(FULL, hs.y, 16);
    o4.z = __shfl_xor_sync(FULL, hs.z, 16);
    o4.w = __shfl_xor_sync(FULL, hs.w, 16);
    float p = hs.x * o4.x + hs.y * o4.y + hs.z * o4.z + hs.w * o4.w;
    p += __shfl_xor_sync(FULL, p, 1);
    p += __shfl_xor_sync(FULL, p, 2);
    float ek = __expf(2.0f * p);
    float Ssim = ek;
    Ssim += __shfl_xor_sync(FULL, Ssim, 4);
    Ssim += __shfl_xor_sync(FULL, Ssim, 8);
    float exp_sim = __expf(sim_k) / Ssim;

    const float4* pr4 = (const float4*)sm;
    float4 pa = pr4[lane * 2];
    float4 pb = pr4[lane * 2 + 1];
    float ad = ra.x * pa.x + ra.y * pa.y + ra.z * pa.z + ra.w * pa.w
             + rb.x * pb.x + rb.y * pb.y + rb.z * pb.z + rb.w * pb.w;
    ad += __shfl_xor_sync(FULL, ad, 1);
    ad += __shfl_xor_sync(FULL, ad, 2);
    ad += __shfl_xor_sync(FULL, ad, 4);
    float eab = __expf(2.0f * ad);
    float Sad = eab;
    Sad += __shfl_xor_sync(FULL, Sad, 8);
    Sad += __shfl_xor_sync(FULL, Sad, 16);
    float e2 = __shfl_sync(FULL, eab, 16);
    float ead = e2 / Sad;

    float g = 1.0f / (1.0f + __expf(-etav));
    ead = g * ead + (1.0f - g) * exp_sim;

    if (lane == 0) {
        g_ead[idx] = ead;
        atomicAdd(&g_norm_u[row], ead);
        atomicAdd(&g_norm_i[col], ead);
    }
}

// ---------------- fused kernel: review projection + weight + scatter (R8) ----------------
__global__ __launch_bounds__(256) void proj_scatter_kernel(
    const float* __restrict__ review_feat,
    const float* __restrict__ review_w_fwd, const float* __restrict__ review_w_rev,
    const int* __restrict__ rows, const int* __restrict__ cols,
    float* __restrict__ int_dist_out)
{
    __shared__ float      smWT[32 * 68];
    __shared__ ulonglong2 smrf[32 * 33];
    __shared__ float      smres[64 * 33];
    const int r = blockIdx.y;
    const int tid = threadIdx.x;

    for (int i = tid; i < 2048; i += 256) {
        int o = i & 31, j = i >> 5;
        float w = (o < 16) ? review_w_fwd[r * 1024 + j * 16 + o]
                           : review_w_rev[r * 1024 + j * 16 + (o - 16)];
        smWT[o * 68 + j] = w;
    }

    const int e0 = blockIdx.x * 64;
    float* smrf_f = (float*)smrf;
    for (int i = tid; i < 1024; i += 256) {
        int e = i >> 4, q = i & 15;
        int eg = e0 + e;
        float4 v = {0,0,0,0};
        if (eg < E_N)
            v = __ldcs((const float4*)(review_feat + ((size_t)r * E_N + eg) * 256 + 128) + q);
        int p = e >> 1, h = e & 1;
        int jf = q * 4;
        int base = (p * 33 + (jf >> 1)) * 4 + h;
        smrf_f[base + 0] = v.x;
        smrf_f[base + 2] = v.y;
        smrf_f[base + 4] = v.z;
        smrf_f[base + 6] = v.w;
    }
    __syncthreads();

    {
        const int lane = tid & 31;
        const int warp = tid >> 5;
        const int pbase = warp * 4;
        unsigned long long acc2[4] = {0ull, 0ull, 0ull, 0ull};
        const float4* wt4 = (const float4*)(smWT + lane * 68);
#pragma unroll
        for (int jq = 0; jq < 16; jq++) {
            float4 wv = wt4[jq];
            unsigned long long w0 = dup2(wv.x), w1 = dup2(wv.y);
            unsigned long long w2 = dup2(wv.z), w3 = dup2(wv.w);
#pragma unroll
            for (int pp = 0; pp < 4; pp++) {
                const ulonglong2* rp = smrf + (pbase + pp) * 33 + jq * 2;
                ulonglong2 rva = rp[0];
                ulonglong2 rvb = rp[1];
                acc2[pp] = fma2(rva.x, w0, acc2[pp]);
                acc2[pp] = fma2(rva.y, w1, acc2[pp]);
                acc2[pp] = fma2(rvb.x, w2, acc2[pp]);
                acc2[pp] = fma2(rvb.y, w3, acc2[pp]);
            }
        }
#pragma unroll
        for (int pp = 0; pp < 4; pp++) {
            float lo, hi;
            unpack2(acc2[pp], lo, hi);
            int el = warp * 8 + 2 * pp;
            smres[el * 33 + lane] = lo;
            smres[(el + 1) * 33 + lane] = hi;
        }
    }
    __syncthreads();

#pragma unroll
    for (int it = 0; it < 2; it++) {
        int item = tid + it * 256;
        int el = item >> 3;
        int q  = item & 7;
        int eg = e0 + el;
        if (eg >= E_N) continue;
        const size_t idx = (size_t)r * E_N + eg;
        const int row = rows[idx];
        const int col = cols[idx];
        const float ead = g_ead[idx];
        const float w = ead * rsqrtf(g_norm_u[row] * g_norm_i[col]);
        if (q == 0) int_dist_out[idx] = w;

        float4 p4;
        float* dest;
        const float* res = smres + el * 33;
        float m0, m1, m2, m3;
        if (q < 4) {
            m0 = res[q*4+0]; m1 = res[q*4+1]; m2 = res[q*4+2]; m3 = res[q*4+3];
            p4 = *(const float4*)(g_P_u + ((size_t)r * U_N + row) * 16 + q * 4);
            dest = g_ifeat + col * 16 + q * 4;
        } else {
            const int qq = q - 4;
            m0 = res[16+qq*4+0]; m1 = res[16+qq*4+1]; m2 = res[16+qq*4+2]; m3 = res[16+qq*4+3];
            p4 = *(const float4*)(g_P_i + ((size_t)r * I_N + col) * 16 + qq * 4);
            dest = g_ufeat + row * 16 + qq * 4;
        }
        float4 mv;
        mv.x = (m0 + p4.x) * w;
        mv.y = (m1 + p4.y) * w;
        mv.z = (m2 + p4.z) * w;
        mv.w = (m3 + p4.w) * w;
        red_v4(dest, mv);
    }
}

// ---------------- kernel 3: leaky + FC (exact R8 version, regs=32) ----------------
#define NB_U ((U_N + 63) / 64)
#define NB_I ((I_N + 63) / 64)
__global__ __launch_bounds__(256) void fc_kernel(
    const float* __restrict__ ufc_w, const float* __restrict__ ufc_b,
    const float* __restrict__ ifc_w, const float* __restrict__ ifc_b,
    float* __restrict__ out)
{
    __shared__ float smx[64 * 17];
    const int tid = threadIdx.x;
    const bool isU = (blockIdx.x < NB_U);
    const int nb = (isU ? blockIdx.x : (blockIdx.x - NB_U)) * 64;
    const int N = isU ? U_N : I_N;
    const float* feat = isU ? g_ufeat : g_ifeat;
    const float* W = isU ? ufc_w : ifc_w;
    const float* B = isU ? ufc_b : ifc_b;
    float* outp = out + (isU ? 0 : (size_t)U_N * 64);

    for (int i = tid; i < 1024; i += 256) {
        int n = i >> 4, j = i & 15;
        int ng = nb + n;
        float x = (ng < N) ? feat[ng * 16 + j] : 0.f;
        x = (x >= 0.f) ? x : 0.1f * x;
        smx[n * 17 + j] = x;
    }
    __syncthreads();

    const int o = tid & 63;
    const int g = tid >> 6;
    float wr[16];
#pragma unroll
    for (int j = 0; j < 16; j++) wr[j] = W[j * 64 + o];
    const float b = B[o];

#pragma unroll
    for (int i = 0; i < 16; i++) {
        int n = g + i * 4;
        int ng = nb + n;
        if (ng < N) {
            float acc = b;
#pragma unroll
            for (int j = 0; j < 16; j++) acc = fmaf(smx[n * 17 + j], wr[j], acc);
            outp[(size_t)ng * 64 + o] = acc;
        }
    }
}

// ---------------- stream/event resources (host-side, created at load; no device mem) ----------------
static cudaStream_t g_side_stream = nullptr;
static cudaEvent_t  g_ev_fork = nullptr;
static cudaEvent_t  g_ev_join = nullptr;
namespace {
struct _StreamInit {
    _StreamInit() {
        cudaStreamCreateWithFlags(&g_side_stream, cudaStreamNonBlocking);
        cudaEventCreateWithFlags(&g_ev_fork, cudaEventDisableTiming);
        cudaEventCreateWithFlags(&g_ev_join, cudaEventDisableTiming);
    }
} _stream_init;
}

// ---------------- launch ----------------
extern "C" void kernel_launch(void* const* d_in, const int* in_sizes, int n_in,
                              void* d_out, int out_size)
{
    const float* user_h       = (const float*)d_in[0];
    const float* item_h       = (const float*)d_in[1];
    const float* user_hsum    = (const float*)d_in[2];
    const float* item_hsum    = (const float*)d_in[3];
    const float* review_feat  = (const float*)d_in[4];
    const float* prototypes   = (const float*)d_in[5];
    const float* eta          = (const float*)d_in[6];
    const float* node_w_fwd   = (const float*)d_in[7];
    const float* node_w_rev   = (const float*)d_in[8];
    const float* review_w_fwd = (const float*)d_in[9];
    const float* review_w_rev = (const float*)d_in[10];
    const float* ufc_w        = (const float*)d_in[11];
    const float* ufc_b        = (const float*)d_in[12];
    const float* ifc_w        = (const float*)d_in[13];
    const float* ifc_b        = (const float*)d_in[14];
    const int*   rows         = (const int*)d_in[15];
    const int*   cols         = (const int*)d_in[16];
    float* out = (float*)d_out;

    // fork: precompute (P only) runs on the side stream, overlapping phase1
    cudaEventRecord(g_ev_fork, 0);
    cudaStreamWaitEvent(g_side_stream, g_ev_fork, 0);
    dim3 pgrid((U_N + 255) / 256, R_N, 2);
    precompute_kernel<<<pgrid, 256, 0, g_side_stream>>>(user_h, item_h,
                                                        node_w_fwd, node_w_rev);
    cudaEventRecord(g_ev_join, g_side_stream);

    // main stream: zero accumulators, then phase1 (independent of precompute)
    zero_kernel<<<(U_N * D_N + 255) / 256, 256>>>();
    dim3 egrid(E_N / 8, R_N);
    phase1_kernel<<<egrid, 256>>>(user_h, item_h, user_hsum, item_hsum,
                                  review_feat, prototypes, eta, rows, cols);

    // join: proj_scatter needs P (side) + norms/ead (main)
    cudaStreamWaitEvent(0, g_ev_join, 0);
    dim3 bgrid((E_N + 63) / 64, R_N);
    proj_scatter_kernel<<<bgrid, 256>>>(review_feat, review_w_fwd, review_w_rev,
                                        rows, cols,
                                        out + (size_t)(U_N + I_N) * OUT_N);

    fc_kernel<<<NB_U + NB_I, 256>>>(ufc_w, ufc_b, ifc_w, ifc_b, out);
}

// round 11
// speedup vs baseline: 1.1059x; 1.0017x over previous
#include <cuda_runtime.h>
#include <cstdint>

#define U_N   100000
#define I_N   50000
#define R_N   5
#define E_N   100000
#define K_N   4
#define D_N   16
#define RD_N  64
#define OUT_N 64
#define KF_N  2
#define PS_EDGES 128

// ---------------- device scratch ----------------
__device__ float g_norm_u[U_N];
__device__ float g_norm_i[I_N];
__device__ float g_ead[R_N * E_N];
__device__ float g_ufeat[U_N * D_N];
__device__ float g_ifeat[I_N * D_N];
__device__ float g_P_u[(size_t)R_N * U_N * D_N];
__device__ float g_P_i[(size_t)R_N * I_N * D_N];

// ---------------- helpers ----------------
__device__ __forceinline__ float red16(float v) {
    v += __shfl_xor_sync(0xffffffffu, v, 1);
    v += __shfl_xor_sync(0xffffffffu, v, 2);
    v += __shfl_xor_sync(0xffffffffu, v, 4);
    v += __shfl_xor_sync(0xffffffffu, v, 8);
    return v;
}
__device__ __forceinline__ void red_v4(float* addr, float4 v) {
    asm volatile("red.global.add.v4.f32 [%0], {%1, %2, %3, %4};"
                 :: "l"(addr), "f"(v.x), "f"(v.y), "f"(v.z), "f"(v.w)
                 : "memory");
}
__device__ __forceinline__ unsigned long long dup2(float v) {
    unsigned long long d;
    asm("mov.b64 %0, {%1, %1};" : "=l"(d) : "f"(v));
    return d;
}
__device__ __forceinline__ unsigned long long fma2(unsigned long long a,
                                                   unsigned long long b,
                                                   unsigned long long c) {
    unsigned long long d;
    asm("fma.rn.f32x2 %0, %1, %2, %3;" : "=l"(d) : "l"(a), "l"(b), "l"(c));
    return d;
}
__device__ __forceinline__ void unpack2(unsigned long long v, float& lo, float& hi) {
    asm("mov.b64 {%0, %1}, %2;" : "=f"(lo), "=f"(hi) : "l"(v));
}

// ---------------- kernel 0: zero accumulators ----------------
__global__ void zero_kernel() {
    int idx = blockIdx.x * 256 + threadIdx.x;
    if (idx < U_N)        g_norm_u[idx] = 0.f;
    if (idx < I_N)        g_norm_i[idx] = 0.f;
    if (idx < U_N * D_N)  g_ufeat[idx]  = 0.f;
    if (idx < I_N * D_N)  g_ifeat[idx]  = 0.f;
}

// ---------------- kernel A: node projection only (side stream) ----------------
__global__ __launch_bounds__(256) void precompute_kernel(
    const float* __restrict__ user_h, const float* __restrict__ item_h,
    const float* __restrict__ node_w_fwd, const float* __restrict__ node_w_rev)
{
    __shared__ float sw[256];
    const int r = blockIdx.y;
    const bool isU = (blockIdx.z == 0);
    const float* W = isU ? node_w_fwd : node_w_rev;
    if (threadIdx.x < 256) sw[threadIdx.x] = W[r * 256 + threadIdx.x];
    __syncthreads();

    const int N = isU ? U_N : I_N;
    const int n = blockIdx.x * 256 + threadIdx.x;
    if (n >= N) return;

    const float* h = (isU ? user_h : item_h) + ((size_t)r * N + n) * 16;
    float xs[16];
    const float4* h4 = (const float4*)h;
    float4 x0 = h4[0], x1 = h4[1], x2 = h4[2], x3 = h4[3];
    xs[0]=x0.x; xs[1]=x0.y; xs[2]=x0.z; xs[3]=x0.w;
    xs[4]=x1.x; xs[5]=x1.y; xs[6]=x1.z; xs[7]=x1.w;
    xs[8]=x2.x; xs[9]=x2.y; xs[10]=x2.z; xs[11]=x2.w;
    xs[12]=x3.x; xs[13]=x3.y; xs[14]=x3.z; xs[15]=x3.w;

    float4 a0 = {0,0,0,0}, a1 = {0,0,0,0}, a2 = {0,0,0,0}, a3 = {0,0,0,0};
    const float4* sw4 = (const float4*)sw;
#pragma unroll
    for (int j = 0; j < 16; j++) {
        float xv = xs[j];
        float4 w0 = sw4[j*4+0], w1 = sw4[j*4+1], w2 = sw4[j*4+2], w3 = sw4[j*4+3];
        a0.x = fmaf(xv, w0.x, a0.x); a0.y = fmaf(xv, w0.y, a0.y);
        a0.z = fmaf(xv, w0.z, a0.z); a0.w = fmaf(xv, w0.w, a0.w);
        a1.x = fmaf(xv, w1.x, a1.x); a1.y = fmaf(xv, w1.y, a1.y);
        a1.z = fmaf(xv, w1.z, a1.z); a1.w = fmaf(xv, w1.w, a1.w);
        a2.x = fmaf(xv, w2.x, a2.x); a2.y = fmaf(xv, w2.y, a2.y);
        a2.z = fmaf(xv, w2.z, a2.z); a2.w = fmaf(xv, w2.w, a2.w);
        a3.x = fmaf(xv, w3.x, a3.x); a3.y = fmaf(xv, w3.y, a3.y);
        a3.z = fmaf(xv, w3.z, a3.z); a3.w = fmaf(xv, w3.w, a3.w);
    }
    float4* P = (float4*)((isU ? g_P_u : g_P_i) + ((size_t)r * N + n) * 16);
    P[0] = a0; P[1] = a1; P[2] = a2; P[3] = a3;
}

// ---------------- kernel 1: per-edge ead (R10 version) ----------------
__global__ __launch_bounds__(256) void phase1_kernel(
    const float* __restrict__ user_h,     const float* __restrict__ item_h,
    const float* __restrict__ user_hsum,  const float* __restrict__ item_hsum,
    const float* __restrict__ review_feat,
    const float* __restrict__ prototypes, const float* __restrict__ eta,
    const int*   __restrict__ rows,       const int*   __restrict__ cols)
{
    __shared__ float sm[256];
    const int r = blockIdx.y;
    if (threadIdx.x < 256) sm[threadIdx.x] = prototypes[threadIdx.x];
    __syncthreads();

    const int lane = threadIdx.x & 31;
    const int warp = threadIdx.x >> 5;
    const int e = blockIdx.x * 8 + warp;
    if (e >= E_N) return;

    const size_t idx = (size_t)r * E_N + e;
    const int row = rows[idx];
    const int col = cols[idx];
    const unsigned FULL = 0xffffffffu;

    const int dh = lane & 15;
    float hval;
    if (lane < 16) hval = __ldg(user_h + ((size_t)r * U_N + row) * 16 + dh);
    else           hval = __ldg(item_h + ((size_t)r * I_N + col) * 16 + dh);

    const float* uh = user_hsum + ((size_t)r * U_N + row) * 64;
    const float* ih = item_hsum + ((size_t)r * I_N + col) * 64;
    float4 hs;
    if (lane < 16) hs = *(const float4*)(uh + 4 * lane);
    else           hs = *(const float4*)(ih + 4 * (lane - 16));

    const float4* rf4 = (const float4*)(review_feat + idx * 256);
    float4 ra = __ldcs(rf4 + lane * 2);
    float4 rb = __ldcs(rf4 + lane * 2 + 1);

    const float etav = eta[idx];

    float othv = __shfl_xor_sync(FULL, hval, 16);
    float dot = red16(hval * othv);
    float ss = red16(hval * hval);
    float oss = __shfl_xor_sync(FULL, ss, 16);
    float sim_k = 2.0f * dot * rsqrtf(ss * oss);

    float4 o4;
    o4.x = __shfl_xor_sync(FULL, hs.x, 16);
    o4.y = __shfl_xor_sync(FULL, hs.y, 16);
    o4.z = __shfl_xor_sync(FULL, hs.z, 16);
    o4.w = __shfl_xor_sync(FULL, hs.w, 16);
    float p = hs.x * o4.x + hs.y * o4.y + hs.z * o4.z + hs.w * o4.w;
    p += __shfl_xor_sync(FULL, p, 1);
    p += __shfl_xor_sync(FULL, p, 2);
    float ek = __expf(2.0f * p);
    float Ssim = ek;
    Ssim += __shfl_xor_sync(FULL, Ssim, 4);
    Ssim += __shfl_xor_sync(FULL, Ssim, 8);
    float exp_sim = __expf(sim_k) / Ssim;

    const float4* pr4 = (const float4*)sm;
    float4 pa = pr4[lane * 2];
    float4 pb = pr4[lane * 2 + 1];
    float ad = ra.x * pa.x + ra.y * pa.y + ra.z * pa.z + ra.w * pa.w
             + rb.x * pb.x + rb.y * pb.y + rb.z * pb.z + rb.w * pb.w;
    ad += __shfl_xor_sync(FULL, ad, 1);
    ad += __shfl_xor_sync(FULL, ad, 2);
    ad += __shfl_xor_sync(FULL, ad, 4);
    float eab = __expf(2.0f * ad);
    float Sad = eab;
    Sad += __shfl_xor_sync(FULL, Sad, 8);
    Sad += __shfl_xor_sync(FULL, Sad, 16);
    float e2 = __shfl_sync(FULL, eab, 16);
    float ead = e2 / Sad;

    float g = 1.0f / (1.0f + __expf(-etav));
    ead = g * ead + (1.0f - g) * exp_sim;

    if (lane == 0) {
        g_ead[idx] = ead;
        atomicAdd(&g_norm_u[row], ead);
        atomicAdd(&g_norm_i[col], ead);
    }
}

// ---------------- fused kernel v2: 128 edges/block, overlay buffer, w-staging ----------------
__global__ __launch_bounds__(256) void proj_scatter_kernel(
    const float* __restrict__ review_feat,
    const float* __restrict__ review_w_fwd, const float* __restrict__ review_w_rev,
    const int* __restrict__ rows, const int* __restrict__ cols,
    float* __restrict__ int_dist_out)
{
    __shared__ float      smWT[32 * 68];            // 8704 B
    __shared__ ulonglong2 smrf[64 * 33];            // 33792 B; overlaid by smres after GEMM
    __shared__ float      smw[PS_EDGES];            // per-edge weight w
    __shared__ int2       smrc[PS_EDGES];           // per-edge (row, col)
    float* smres = (float*)smrf;                    // [128][33] floats (16896 B) fits

    const int r = blockIdx.y;
    const int tid = threadIdx.x;
    const int e0 = blockIdx.x * PS_EDGES;

    // ---- stage weights ----
    for (int i = tid; i < 2048; i += 256) {
        int o = i & 31, j = i >> 5;
        float w = (o < 16) ? review_w_fwd[r * 1024 + j * 16 + o]
                           : review_w_rev[r * 1024 + j * 16 + (o - 16)];
        smWT[o * 68 + j] = w;
    }

    // ---- stage rf_k for 128 edges, pair-packed ----
    float* smrf_f = (float*)smrf;
    for (int i = tid; i < 2048; i += 256) {
        int e = i >> 4, q = i & 15;
        int eg = e0 + e;
        float4 v = {0,0,0,0};
        if (eg < E_N)
            v = __ldcs((const float4*)(review_feat + ((size_t)r * E_N + eg) * 256 + 128) + q);
        int p = e >> 1, h = e & 1;
        int base = (p * 33 + q * 2) * 4 + h;
        smrf_f[base + 0] = v.x;
        smrf_f[base + 2] = v.y;
        smrf_f[base + 4] = v.z;
        smrf_f[base + 6] = v.w;
    }

    // ---- w-stage: one thread per edge computes w, caches (row,col,w) ----
    if (tid < PS_EDGES) {
        int eg = e0 + tid;
        if (eg < E_N) {
            const size_t idx = (size_t)r * E_N + eg;
            const int row = rows[idx];
            const int col = cols[idx];
            const float ead = g_ead[idx];
            const float w = ead * rsqrtf(g_norm_u[row] * g_norm_i[col]);
            int_dist_out[idx] = w;
            smw[tid] = w;
            smrc[tid] = make_int2(row, col);
        }
    }
    __syncthreads();

    // ---- GEMM: warp owns 8 pairs (16 edges) x 32 outs, FFMA2 ----
    const int lane = tid & 31;
    const int warp = tid >> 5;
    {
        const int pbase = warp * 8;
        unsigned long long acc2[8] = {0ull,0ull,0ull,0ull,0ull,0ull,0ull,0ull};
        const float4* wt4 = (const float4*)(smWT + lane * 68);
#pragma unroll
        for (int jq = 0; jq < 16; jq++) {
            float4 wv = wt4[jq];
            unsigned long long w0 = dup2(wv.x), w1 = dup2(wv.y);
            unsigned long long w2 = dup2(wv.z), w3 = dup2(wv.w);
#pragma unroll
            for (int pp = 0; pp < 8; pp++) {
                const ulonglong2* rp = smrf + (pbase + pp) * 33 + jq * 2;
                ulonglong2 rva = rp[0];
                ulonglong2 rvb = rp[1];
                acc2[pp] = fma2(rva.x, w0, acc2[pp]);
                acc2[pp] = fma2(rva.y, w1, acc2[pp]);
                acc2[pp] = fma2(rvb.x, w2, acc2[pp]);
                acc2[pp] = fma2(rvb.y, w3, acc2[pp]);
            }
        }
        __syncthreads();   // all smrf reads complete before overlay store
#pragma unroll
        for (int pp = 0; pp < 8; pp++) {
            float lo, hi;
            unpack2(acc2[pp], lo, hi);
            int el = warp * 16 + 2 * pp;
            smres[el * 33 + lane] = lo;
            smres[(el + 1) * 33 + lane] = hi;
        }
    }
    __syncthreads();

    // ---- scatter: 128 edges x 8 threads = 1024 items ----
#pragma unroll
    for (int it = 0; it < 4; it++) {
        int item = tid + it * 256;
        int el = item >> 3;
        int q  = item & 7;
        int eg = e0 + el;
        if (eg >= E_N) continue;
        const float w = smw[el];
        const int2 rc = smrc[el];

        float4 p4;
        float* dest;
        const float* res = smres + el * 33;
        float m0, m1, m2, m3;
        if (q < 4) {
            m0 = res[q*4+0]; m1 = res[q*4+1]; m2 = res[q*4+2]; m3 = res[q*4+3];
            p4 = *(const float4*)(g_P_u + ((size_t)r * U_N + rc.x) * 16 + q * 4);
            dest = g_ifeat + rc.y * 16 + q * 4;
        } else {
            const int qq = q - 4;
            m0 = res[16+qq*4+0]; m1 = res[16+qq*4+1]; m2 = res[16+qq*4+2]; m3 = res[16+qq*4+3];
            p4 = *(const float4*)(g_P_i + ((size_t)r * I_N + rc.y) * 16 + qq * 4);
            dest = g_ufeat + rc.x * 16 + qq * 4;
        }
        float4 mv;
        mv.x = (m0 + p4.x) * w;
        mv.y = (m1 + p4.y) * w;
        mv.z = (m2 + p4.z) * w;
        mv.w = (m3 + p4.w) * w;
        red_v4(dest, mv);
    }
}

// ---------------- kernel 3: leaky + FC (R8 version) ----------------
#define NB_U ((U_N + 63) / 64)
#define NB_I ((I_N + 63) / 64)
__global__ __launch_bounds__(256) void fc_kernel(
    const float* __restrict__ ufc_w, const float* __restrict__ ufc_b,
    const float* __restrict__ ifc_w, const float* __restrict__ ifc_b,
    float* __restrict__ out)
{
    __shared__ float smx[64 * 17];
    const int tid = threadIdx.x;
    const bool isU = (blockIdx.x < NB_U);
    const int nb = (isU ? blockIdx.x : (blockIdx.x - NB_U)) * 64;
    const int N = isU ? U_N : I_N;
    const float* feat = isU ? g_ufeat : g_ifeat;
    const float* W = isU ? ufc_w : ifc_w;
    const float* B = isU ? ufc_b : ifc_b;
    float* outp = out + (isU ? 0 : (size_t)U_N * 64);

    for (int i = tid; i < 1024; i += 256) {
        int n = i >> 4, j = i & 15;
        int ng = nb + n;
        float x = (ng < N) ? feat[ng * 16 + j] : 0.f;
        x = (x >= 0.f) ? x : 0.1f * x;
        smx[n * 17 + j] = x;
    }
    __syncthreads();

    const int o = tid & 63;
    const int g = tid >> 6;
    float wr[16];
#pragma unroll
    for (int j = 0; j < 16; j++) wr[j] = W[j * 64 + o];
    const float b = B[o];

#pragma unroll
    for (int i = 0; i < 16; i++) {
        int n = g + i * 4;
        int ng = nb + n;
        if (ng < N) {
            float acc = b;
#pragma unroll
            for (int j = 0; j < 16; j++) acc = fmaf(smx[n * 17 + j], wr[j], acc);
            outp[(size_t)ng * 64 + o] = acc;
        }
    }
}

// ---------------- stream/event resources ----------------
static cudaStream_t g_side_stream = nullptr;
static cudaEvent_t  g_ev_fork = nullptr;
static cudaEvent_t  g_ev_join = nullptr;
namespace {
struct _StreamInit {
    _StreamInit() {
        cudaStreamCreateWithFlags(&g_side_stream, cudaStreamNonBlocking);
        cudaEventCreateWithFlags(&g_ev_fork, cudaEventDisableTiming);
        cudaEventCreateWithFlags(&g_ev_join, cudaEventDisableTiming);
    }
} _stream_init;
}

// ---------------- launch ----------------
extern "C" void kernel_launch(void* const* d_in, const int* in_sizes, int n_in,
                              void* d_out, int out_size)
{
    const float* user_h       = (const float*)d_in[0];
    const float* item_h       = (const float*)d_in[1];
    const float* user_hsum    = (const float*)d_in[2];
    const float* item_hsum    = (const float*)d_in[3];
    const float* review_feat  = (const float*)d_in[4];
    const float* prototypes   = (const float*)d_in[5];
    const float* eta          = (const float*)d_in[6];
    const float* node_w_fwd   = (const float*)d_in[7];
    const float* node_w_rev   = (const float*)d_in[8];
    const float* review_w_fwd = (const float*)d_in[9];
    const float* review_w_rev = (const float*)d_in[10];
    const float* ufc_w        = (const float*)d_in[11];
    const float* ufc_b        = (const float*)d_in[12];
    const float* ifc_w        = (const float*)d_in[13];
    const float* ifc_b        = (const float*)d_in[14];
    const int*   rows         = (const int*)d_in[15];
    const int*   cols         = (const int*)d_in[16];
    float* out = (float*)d_out;

    // fork: precompute on side stream, overlapping phase1
    cudaEventRecord(g_ev_fork, 0);
    cudaStreamWaitEvent(g_side_stream, g_ev_fork, 0);
    dim3 pgrid((U_N + 255) / 256, R_N, 2);
    precompute_kernel<<<pgrid, 256, 0, g_side_stream>>>(user_h, item_h,
                                                        node_w_fwd, node_w_rev);
    cudaEventRecord(g_ev_join, g_side_stream);

    zero_kernel<<<(U_N * D_N + 255) / 256, 256>>>();
    dim3 egrid(E_N / 8, R_N);
    phase1_kernel<<<egrid, 256>>>(user_h, item_h, user_hsum, item_hsum,
                                  review_feat, prototypes, eta, rows, cols);

    cudaStreamWaitEvent(0, g_ev_join, 0);
    dim3 bgrid((E_N + PS_EDGES - 1) / PS_EDGES, R_N);
    proj_scatter_kernel<<<bgrid, 256>>>(review_feat, review_w_fwd, review_w_rev,
                                        rows, cols,
                                        out + (size_t)(U_N + I_N) * OUT_N);

    fc_kernel<<<NB_U + NB_I, 256>>>(ufc_w, ufc_b, ifc_w, ifc_b, out);
}

// round 12
// speedup vs baseline: 1.1153x; 1.0085x over previous
#include <cuda_runtime.h>
#include <cstdint>

#define U_N   100000
#define I_N   50000
#define R_N   5
#define E_N   100000
#define K_N   4
#define D_N   16
#define RD_N  64
#define OUT_N 64
#define KF_N  2
#define PS_EDGES 64

// ---------------- device scratch ----------------
__device__ float g_norm_u[U_N];
__device__ float g_norm_i[I_N];
__device__ float g_ead[R_N * E_N];
__device__ float g_ufeat[U_N * D_N];
__device__ float g_ifeat[I_N * D_N];
__device__ float g_P_u[(size_t)R_N * U_N * D_N];
__device__ float g_P_i[(size_t)R_N * I_N * D_N];

// ---------------- helpers ----------------
__device__ __forceinline__ float red16(float v) {
    v += __shfl_xor_sync(0xffffffffu, v, 1);
    v += __shfl_xor_sync(0xffffffffu, v, 2);
    v += __shfl_xor_sync(0xffffffffu, v, 4);
    v += __shfl_xor_sync(0xffffffffu, v, 8);
    return v;
}
__device__ __forceinline__ void red_v4(float* addr, float4 v) {
    asm volatile("red.global.add.v4.f32 [%0], {%1, %2, %3, %4};"
                 :: "l"(addr), "f"(v.x), "f"(v.y), "f"(v.z), "f"(v.w)
                 : "memory");
}
__device__ __forceinline__ unsigned long long dup2(float v) {
    unsigned long long d;
    asm("mov.b64 %0, {%1, %1};" : "=l"(d) : "f"(v));
    return d;
}
__device__ __forceinline__ unsigned long long fma2(unsigned long long a,
                                                   unsigned long long b,
                                                   unsigned long long c) {
    unsigned long long d;
    asm("fma.rn.f32x2 %0, %1, %2, %3;" : "=l"(d) : "l"(a), "l"(b), "l"(c));
    return d;
}
__device__ __forceinline__ void unpack2(unsigned long long v, float& lo, float& hi) {
    asm("mov.b64 {%0, %1}, %2;" : "=f"(lo), "=f"(hi) : "l"(v));
}

// ---------------- kernel 0: zero accumulators ----------------
__global__ void zero_kernel() {
    int idx = blockIdx.x * 256 + threadIdx.x;
    if (idx < U_N)        g_norm_u[idx] = 0.f;
    if (idx < I_N)        g_norm_i[idx] = 0.f;
    if (idx < U_N * D_N)  g_ufeat[idx]  = 0.f;
    if (idx < I_N * D_N)  g_ifeat[idx]  = 0.f;
}

// ---------------- kernel A: node projection only (side stream) ----------------
__global__ __launch_bounds__(256) void precompute_kernel(
    const float* __restrict__ user_h, const float* __restrict__ item_h,
    const float* __restrict__ node_w_fwd, const float* __restrict__ node_w_rev)
{
    __shared__ float sw[256];
    const int r = blockIdx.y;
    const bool isU = (blockIdx.z == 0);
    const float* W = isU ? node_w_fwd : node_w_rev;
    if (threadIdx.x < 256) sw[threadIdx.x] = W[r * 256 + threadIdx.x];
    __syncthreads();

    const int N = isU ? U_N : I_N;
    const int n = blockIdx.x * 256 + threadIdx.x;
    if (n >= N) return;

    const float* h = (isU ? user_h : item_h) + ((size_t)r * N + n) * 16;
    float xs[16];
    const float4* h4 = (const float4*)h;
    float4 x0 = h4[0], x1 = h4[1], x2 = h4[2], x3 = h4[3];
    xs[0]=x0.x; xs[1]=x0.y; xs[2]=x0.z; xs[3]=x0.w;
    xs[4]=x1.x; xs[5]=x1.y; xs[6]=x1.z; xs[7]=x1.w;
    xs[8]=x2.x; xs[9]=x2.y; xs[10]=x2.z; xs[11]=x2.w;
    xs[12]=x3.x; xs[13]=x3.y; xs[14]=x3.z; xs[15]=x3.w;

    float4 a0 = {0,0,0,0}, a1 = {0,0,0,0}, a2 = {0,0,0,0}, a3 = {0,0,0,0};
    const float4* sw4 = (const float4*)sw;
#pragma unroll
    for (int j = 0; j < 16; j++) {
        float xv = xs[j];
        float4 w0 = sw4[j*4+0], w1 = sw4[j*4+1], w2 = sw4[j*4+2], w3 = sw4[j*4+3];
        a0.x = fmaf(xv, w0.x, a0.x); a0.y = fmaf(xv, w0.y, a0.y);
        a0.z = fmaf(xv, w0.z, a0.z); a0.w = fmaf(xv, w0.w, a0.w);
        a1.x = fmaf(xv, w1.x, a1.x); a1.y = fmaf(xv, w1.y, a1.y);
        a1.z = fmaf(xv, w1.z, a1.z); a1.w = fmaf(xv, w1.w, a1.w);
        a2.x = fmaf(xv, w2.x, a2.x); a2.y = fmaf(xv, w2.y, a2.y);
        a2.z = fmaf(xv, w2.z, a2.z); a2.w = fmaf(xv, w2.w, a2.w);
        a3.x = fmaf(xv, w3.x, a3.x); a3.y = fmaf(xv, w3.y, a3.y);
        a3.z = fmaf(xv, w3.z, a3.z); a3.w = fmaf(xv, w3.w, a3.w);
    }
    float4* P = (float4*)((isU ? g_P_u : g_P_i) + ((size_t)r * N + n) * 16);
    P[0] = a0; P[1] = a1; P[2] = a2; P[3] = a3;
}

// ---------------- kernel 1: per-edge ead (R10 version) ----------------
__global__ __launch_bounds__(256) void phase1_kernel(
    const float* __restrict__ user_h,     const float* __restrict__ item_h,
    const float* __restrict__ user_hsum,  const float* __restrict__ item_hsum,
    const float* __restrict__ review_feat,
    const float* __restrict__ prototypes, const float* __restrict__ eta,
    const int*   __restrict__ rows,       const int*   __restrict__ cols)
{
    __shared__ float sm[256];
    const int r = blockIdx.y;
    if (threadIdx.x < 256) sm[threadIdx.x] = prototypes[threadIdx.x];
    __syncthreads();

    const int lane = threadIdx.x & 31;
    const int warp = threadIdx.x >> 5;
    const int e = blockIdx.x * 8 + warp;
    if (e >= E_N) return;

    const size_t idx = (size_t)r * E_N + e;
    const int row = rows[idx];
    const int col = cols[idx];
    const unsigned FULL = 0xffffffffu;

    const int dh = lane & 15;
    float hval;
    if (lane < 16) hval = __ldg(user_h + ((size_t)r * U_N + row) * 16 + dh);
    else           hval = __ldg(item_h + ((size_t)r * I_N + col) * 16 + dh);

    const float* uh = user_hsum + ((size_t)r * U_N + row) * 64;
    const float* ih = item_hsum + ((size_t)r * I_N + col) * 64;
    float4 hs;
    if (lane < 16) hs = *(const float4*)(uh + 4 * lane);
    else           hs = *(const float4*)(ih + 4 * (lane - 16));

    const float4* rf4 = (const float4*)(review_feat + idx * 256);
    float4 ra = __ldcs(rf4 + lane * 2);
    float4 rb = __ldcs(rf4 + lane * 2 + 1);

    const float etav = eta[idx];

    float othv = __shfl_xor_sync(FULL, hval, 16);
    float dot = red16(hval * othv);
    float ss = red16(hval * hval);
    float oss = __shfl_xor_sync(FULL, ss, 16);
    float sim_k = 2.0f * dot * rsqrtf(ss * oss);

    float4 o4;
    o4.x = __shfl_xor_sync(FULL, hs.x, 16);
    o4.y = __shfl_xor_sync(FULL, hs.y, 16);
    o4.z = __shfl_xor_sync(FULL, hs.z, 16);
    o4.w = __shfl_xor_sync(FULL, hs.w, 16);
    float p = hs.x * o4.x + hs.y * o4.y + hs.z * o4.z + hs.w * o4.w;
    p += __shfl_xor_sync(FULL, p, 1);
    p += __shfl_xor_sync(FULL, p, 2);
    float ek = __expf(2.0f * p);
    float Ssim = ek;
    Ssim += __shfl_xor_sync(FULL, Ssim, 4);
    Ssim += __shfl_xor_sync(FULL, Ssim, 8);
    float exp_sim = __expf(sim_k) / Ssim;

    const float4* pr4 = (const float4*)sm;
    float4 pa = pr4[lane * 2];
    float4 pb = pr4[lane * 2 + 1];
    float ad = ra.x * pa.x + ra.y * pa.y + ra.z * pa.z + ra.w * pa.w
             + rb.x * pb.x + rb.y * pb.y + rb.z * pb.z + rb.w * pb.w;
    ad += __shfl_xor_sync(FULL, ad, 1);
    ad += __shfl_xor_sync(FULL, ad, 2);
    ad += __shfl_xor_sync(FULL, ad, 4);
    float eab = __expf(2.0f * ad);
    float Sad = eab;
    Sad += __shfl_xor_sync(FULL, Sad, 8);
    Sad += __shfl_xor_sync(FULL, Sad, 16);
    float e2 = __shfl_sync(FULL, eab, 16);
    float ead = e2 / Sad;

    float g = 1.0f / (1.0f + __expf(-etav));
    ead = g * ead + (1.0f - g) * exp_sim;

    if (lane == 0) {
        g_ead[idx] = ead;
        atomicAdd(&g_norm_u[row], ead);
        atomicAdd(&g_norm_i[col], ead);
    }
}

// ---------------- fused kernel v3: wide-LDS lane mapping, 64 edges/block ----------------
// Warp owns 4 pairs (8 edges) x 32 outs. Lane = (pair_local = lane>>3, o4 = lane&7).
// All LDS are full-width wavefronts: rf 4x16B distinct (1 wf), weights 8x16B = 128B (1 wf).
__global__ __launch_bounds__(256) void proj_scatter_kernel(
    const float* __restrict__ review_feat,
    const float* __restrict__ review_w_fwd, const float* __restrict__ review_w_rev,
    const int* __restrict__ rows, const int* __restrict__ cols,
    float* __restrict__ int_dist_out)
{
    __shared__ float      smW[64 * 36];             // [j][o], stride 36 (f4-aligned, conflict-free)
    __shared__ ulonglong2 smrf[32 * 33];            // [pair][j/2], stride 33 units
    __shared__ float      smw[PS_EDGES];
    __shared__ int2       smrc[PS_EDGES];
    float* smres = (float*)smrf;                    // overlay after GEMM: [64][33] floats

    const int r = blockIdx.y;
    const int tid = threadIdx.x;
    const int e0 = blockIdx.x * PS_EDGES;

    // ---- stage weights: smW[j*36 + o] ----
    for (int i = tid; i < 2048; i += 256) {
        int o = i & 31, j = i >> 5;
        float w = (o < 16) ? review_w_fwd[r * 1024 + j * 16 + o]
                           : review_w_rev[r * 1024 + j * 16 + (o - 16)];
        smW[j * 36 + o] = w;
    }

    // ---- stage rf_k for 64 edges, pair-packed (even/odd edge per f32x2) ----
    float* smrf_f = (float*)smrf;
    for (int i = tid; i < 1024; i += 256) {
        int e = i >> 4, q = i & 15;
        int eg = e0 + e;
        float4 v = {0,0,0,0};
        if (eg < E_N)
            v = __ldcs((const float4*)(review_feat + ((size_t)r * E_N + eg) * 256 + 128) + q);
        int p = e >> 1, h = e & 1;
        int base = (p * 33 + q * 2) * 4 + h;
        smrf_f[base + 0] = v.x;
        smrf_f[base + 2] = v.y;
        smrf_f[base + 4] = v.z;
        smrf_f[base + 6] = v.w;
    }

    // ---- w-stage: one thread per edge ----
    if (tid < PS_EDGES) {
        int eg = e0 + tid;
        if (eg < E_N) {
            const size_t idx = (size_t)r * E_N + eg;
            const int row = rows[idx];
            const int col = cols[idx];
            const float ead = g_ead[idx];
            const float w = ead * rsqrtf(g_norm_u[row] * g_norm_i[col]);
            int_dist_out[idx] = w;
            smw[tid] = w;
            smrc[tid] = make_int2(row, col);
        }
    }
    __syncthreads();

    // ---- GEMM ----
    const int lane = tid & 31;
    const int warp = tid >> 5;
    const int p_local = lane >> 3;          // 0..3
    const int o4 = lane & 7;                // output quad index
    const int pair = warp * 4 + p_local;    // 0..31
    {
        unsigned long long acc2[4] = {0ull, 0ull, 0ull, 0ull};
        const ulonglong2* rfp = smrf + pair * 33;
        const float* wp = smW + o4 * 4;
#pragma unroll
        for (int jq = 0; jq < 16; jq++) {
            ulonglong2 rva = rfp[jq * 2];       // j = 4jq (x), 4jq+1 (y)
            ulonglong2 rvb = rfp[jq * 2 + 1];   // j = 4jq+2 (x), 4jq+3 (y)
            float4 w0 = *(const float4*)(wp + (4*jq+0) * 36);
            float4 w1 = *(const float4*)(wp + (4*jq+1) * 36);
            float4 w2 = *(const float4*)(wp + (4*jq+2) * 36);
            float4 w3 = *(const float4*)(wp + (4*jq+3) * 36);
            acc2[0] = fma2(rva.x, dup2(w0.x), acc2[0]);
            acc2[1] = fma2(rva.x, dup2(w0.y), acc2[1]);
            acc2[2] = fma2(rva.x, dup2(w0.z), acc2[2]);
            acc2[3] = fma2(rva.x, dup2(w0.w), acc2[3]);
            acc2[0] = fma2(rva.y, dup2(w1.x), acc2[0]);
            acc2[1] = fma2(rva.y, dup2(w1.y), acc2[1]);
            acc2[2] = fma2(rva.y, dup2(w1.z), acc2[2]);
            acc2[3] = fma2(rva.y, dup2(w1.w), acc2[3]);
            acc2[0] = fma2(rvb.x, dup2(w2.x), acc2[0]);
            acc2[1] = fma2(rvb.x, dup2(w2.y), acc2[1]);
            acc2[2] = fma2(rvb.x, dup2(w2.z), acc2[2]);
            acc2[3] = fma2(rvb.x, dup2(w2.w), acc2[3]);
            acc2[0] = fma2(rvb.y, dup2(w3.x), acc2[0]);
            acc2[1] = fma2(rvb.y, dup2(w3.y), acc2[1]);
            acc2[2] = fma2(rvb.y, dup2(w3.z), acc2[2]);
            acc2[3] = fma2(rvb.y, dup2(w3.w), acc2[3]);
        }
        __syncthreads();   // all smrf reads done before overlay stores

        const int el = pair * 2;
#pragma unroll
        for (int oo = 0; oo < 4; oo++) {
            float lo, hi;
            unpack2(acc2[oo], lo, hi);
            smres[el * 33 + o4 * 4 + oo] = lo;
            smres[(el + 1) * 33 + o4 * 4 + oo] = hi;
        }
    }
    __syncthreads();

    // ---- scatter: 64 edges x 8 threads = 512 items ----
#pragma unroll
    for (int it = 0; it < 2; it++) {
        int item = tid + it * 256;
        int el = item >> 3;
        int q  = item & 7;
        int eg = e0 + el;
        if (eg >= E_N) continue;
        const float w = smw[el];
        const int2 rc = smrc[el];

        float4 p4;
        float* dest;
        const float* res = smres + el * 33;
        float m0, m1, m2, m3;
        if (q < 4) {
            m0 = res[q*4+0]; m1 = res[q*4+1]; m2 = res[q*4+2]; m3 = res[q*4+3];
            p4 = *(const float4*)(g_P_u + ((size_t)r * U_N + rc.x) * 16 + q * 4);
            dest = g_ifeat + rc.y * 16 + q * 4;
        } else {
            const int qq = q - 4;
            m0 = res[16+qq*4+0]; m1 = res[16+qq*4+1]; m2 = res[16+qq*4+2]; m3 = res[16+qq*4+3];
            p4 = *(const float4*)(g_P_i + ((size_t)r * I_N + rc.y) * 16 + qq * 4);
            dest = g_ufeat + rc.x * 16 + qq * 4;
        }
        float4 mv;
        mv.x = (m0 + p4.x) * w;
        mv.y = (m1 + p4.y) * w;
        mv.z = (m2 + p4.z) * w;
        mv.w = (m3 + p4.w) * w;
        red_v4(dest, mv);
    }
}

// ---------------- kernel 3: leaky + FC (R8 version) ----------------
#define NB_U ((U_N + 63) / 64)
#define NB_I ((I_N + 63) / 64)
__global__ __launch_bounds__(256) void fc_kernel(
    const float* __restrict__ ufc_w, const float* __restrict__ ufc_b,
    const float* __restrict__ ifc_w, const float* __restrict__ ifc_b,
    float* __restrict__ out)
{
    __shared__ float smx[64 * 17];
    const int tid = threadIdx.x;
    const bool isU = (blockIdx.x < NB_U);
    const int nb = (isU ? blockIdx.x : (blockIdx.x - NB_U)) * 64;
    const int N = isU ? U_N : I_N;
    const float* feat = isU ? g_ufeat : g_ifeat;
    const float* W = isU ? ufc_w : ifc_w;
    const float* B = isU ? ufc_b : ifc_b;
    float* outp = out + (isU ? 0 : (size_t)U_N * 64);

    for (int i = tid; i < 1024; i += 256) {
        int n = i >> 4, j = i & 15;
        int ng = nb + n;
        float x = (ng < N) ? feat[ng * 16 + j] : 0.f;
        x = (x >= 0.f) ? x : 0.1f * x;
        smx[n * 17 + j] = x;
    }
    __syncthreads();

    const int o = tid & 63;
    const int g = tid >> 6;
    float wr[16];
#pragma unroll
    for (int j = 0; j < 16; j++) wr[j] = W[j * 64 + o];
    const float b = B[o];

#pragma unroll
    for (int i = 0; i < 16; i++) {
        int n = g + i * 4;
        int ng = nb + n;
        if (ng < N) {
            float acc = b;
#pragma unroll
            for (int j = 0; j < 16; j++) acc = fmaf(smx[n * 17 + j], wr[j], acc);
            outp[(size_t)ng * 64 + o] = acc;
        }
    }
}

// ---------------- stream/event resources ----------------
static cudaStream_t g_side_stream = nullptr;
static cudaEvent_t  g_ev_fork = nullptr;
static cudaEvent_t  g_ev_join = nullptr;
namespace {
struct _StreamInit {
    _StreamInit() {
        cudaStreamCreateWithFlags(&g_side_stream, cudaStreamNonBlocking);
        cudaEventCreateWithFlags(&g_ev_fork, cudaEventDisableTiming);
        cudaEventCreateWithFlags(&g_ev_join, cudaEventDisableTiming);
    }
} _stream_init;
}

// ---------------- launch ----------------
extern "C" void kernel_launch(void* const* d_in, const int* in_sizes, int n_in,
                              void* d_out, int out_size)
{
    const float* user_h       = (const float*)d_in[0];
    const float* item_h       = (const float*)d_in[1];
    const float* user_hsum    = (const float*)d_in[2];
    const float* item_hsum    = (const float*)d_in[3];
    const float* review_feat  = (const float*)d_in[4];
    const float* prototypes   = (const float*)d_in[5];
    const float* eta          = (const float*)d_in[6];
    const float* node_w_fwd   = (const float*)d_in[7];
    const float* node_w_rev   = (const float*)d_in[8];
    const float* review_w_fwd = (const float*)d_in[9];
    const float* review_w_rev = (const float*)d_in[10];
    const float* ufc_w        = (const float*)d_in[11];
    const float* ufc_b        = (const float*)d_in[12];
    const float* ifc_w        = (const float*)d_in[13];
    const float* ifc_b        = (const float*)d_in[14];
    const int*   rows         = (const int*)d_in[15];
    const int*   cols         = (const int*)d_in[16];
    float* out = (float*)d_out;

    // fork: precompute on side stream, overlapping phase1
    cudaEventRecord(g_ev_fork, 0);
    cudaStreamWaitEvent(g_side_stream, g_ev_fork, 0);
    dim3 pgrid((U_N + 255) / 256, R_N, 2);
    precompute_kernel<<<pgrid, 256, 0, g_side_stream>>>(user_h, item_h,
                                                        node_w_fwd, node_w_rev);
    cudaEventRecord(g_ev_join, g_side_stream);

    zero_kernel<<<(U_N * D_N + 255) / 256, 256>>>();
    dim3 egrid(E_N / 8, R_N);
    phase1_kernel<<<egrid, 256>>>(user_h, item_h, user_hsum, item_hsum,
                                  review_feat, prototypes, eta, rows, cols);

    cudaStreamWaitEvent(0, g_ev_join, 0);
    dim3 bgrid((E_N + PS_EDGES - 1) / PS_EDGES, R_N);
    proj_scatter_kernel<<<bgrid, 256>>>(review_feat, review_w_fwd, review_w_rev,
                                        rows, cols,
                                        out + (size_t)(U_N + I_N) * OUT_N);

    fc_kernel<<<NB_U + NB_I, 256>>>(ufc_w, ufc_b, ifc_w, ifc_b, out);
}

// round 13
// speedup vs baseline: 1.1536x; 1.0343x over previous
#include <cuda_runtime.h>
#include <cstdint>

#define U_N   100000
#define I_N   50000
#define R_N   5
#define E_N   100000
#define K_N   4
#define D_N   16
#define RD_N  64
#define OUT_N 64
#define KF_N  2
#define PS_EDGES 64

// ---------------- device scratch ----------------
__device__ float g_norm_u[U_N];
__device__ float g_norm_i[I_N];
__device__ float g_ead[R_N * E_N];
__device__ float g_ufeat[U_N * D_N];
__device__ float g_ifeat[I_N * D_N];
__device__ float g_P_u[(size_t)R_N * U_N * D_N];
__device__ float g_P_i[(size_t)R_N * I_N * D_N];

// ---------------- helpers ----------------
__device__ __forceinline__ float red16(float v) {
    v += __shfl_xor_sync(0xffffffffu, v, 1);
    v += __shfl_xor_sync(0xffffffffu, v, 2);
    v += __shfl_xor_sync(0xffffffffu, v, 4);
    v += __shfl_xor_sync(0xffffffffu, v, 8);
    return v;
}
__device__ __forceinline__ void red_v4(float* addr, float4 v) {
    asm volatile("red.global.add.v4.f32 [%0], {%1, %2, %3, %4};"
                 :: "l"(addr), "f"(v.x), "f"(v.y), "f"(v.z), "f"(v.w)
                 : "memory");
}
__device__ __forceinline__ unsigned long long dup2(float v) {
    unsigned long long d;
    asm("mov.b64 %0, {%1, %1};" : "=l"(d) : "f"(v));
    return d;
}
__device__ __forceinline__ unsigned long long pack2(float lo, float hi) {
    unsigned long long d;
    asm("mov.b64 %0, {%1, %2};" : "=l"(d) : "f"(lo), "f"(hi));
    return d;
}
__device__ __forceinline__ unsigned long long fma2(unsigned long long a,
                                                   unsigned long long b,
                                                   unsigned long long c) {
    unsigned long long d;
    asm("fma.rn.f32x2 %0, %1, %2, %3;" : "=l"(d) : "l"(a), "l"(b), "l"(c));
    return d;
}
__device__ __forceinline__ void unpack2(unsigned long long v, float& lo, float& hi) {
    asm("mov.b64 {%0, %1}, %2;" : "=f"(lo), "=f"(hi) : "l"(v));
}

// ---------------- kernel 0: zero accumulators ----------------
__global__ void zero_kernel() {
    int idx = blockIdx.x * 256 + threadIdx.x;
    if (idx < U_N)        g_norm_u[idx] = 0.f;
    if (idx < I_N)        g_norm_i[idx] = 0.f;
    if (idx < U_N * D_N)  g_ufeat[idx]  = 0.f;
    if (idx < I_N * D_N)  g_ifeat[idx]  = 0.f;
}

// ---------------- kernel A: node projection only (side stream) ----------------
__global__ __launch_bounds__(256) void precompute_kernel(
    const float* __restrict__ user_h, const float* __restrict__ item_h,
    const float* __restrict__ node_w_fwd, const float* __restrict__ node_w_rev)
{
    __shared__ float sw[256];
    const int r = blockIdx.y;
    const bool isU = (blockIdx.z == 0);
    const float* W = isU ? node_w_fwd : node_w_rev;
    if (threadIdx.x < 256) sw[threadIdx.x] = W[r * 256 + threadIdx.x];
    __syncthreads();

    const int N = isU ? U_N : I_N;
    const int n = blockIdx.x * 256 + threadIdx.x;
    if (n >= N) return;

    const float* h = (isU ? user_h : item_h) + ((size_t)r * N + n) * 16;
    float xs[16];
    const float4* h4 = (const float4*)h;
    float4 x0 = h4[0], x1 = h4[1], x2 = h4[2], x3 = h4[3];
    xs[0]=x0.x; xs[1]=x0.y; xs[2]=x0.z; xs[3]=x0.w;
    xs[4]=x1.x; xs[5]=x1.y; xs[6]=x1.z; xs[7]=x1.w;
    xs[8]=x2.x; xs[9]=x2.y; xs[10]=x2.z; xs[11]=x2.w;
    xs[12]=x3.x; xs[13]=x3.y; xs[14]=x3.z; xs[15]=x3.w;

    float4 a0 = {0,0,0,0}, a1 = {0,0,0,0}, a2 = {0,0,0,0}, a3 = {0,0,0,0};
    const float4* sw4 = (const float4*)sw;
#pragma unroll
    for (int j = 0; j < 16; j++) {
        float xv = xs[j];
        float4 w0 = sw4[j*4+0], w1 = sw4[j*4+1], w2 = sw4[j*4+2], w3 = sw4[j*4+3];
        a0.x = fmaf(xv, w0.x, a0.x); a0.y = fmaf(xv, w0.y, a0.y);
        a0.z = fmaf(xv, w0.z, a0.z); a0.w = fmaf(xv, w0.w, a0.w);
        a1.x = fmaf(xv, w1.x, a1.x); a1.y = fmaf(xv, w1.y, a1.y);
        a1.z = fmaf(xv, w1.z, a1.z); a1.w = fmaf(xv, w1.w, a1.w);
        a2.x = fmaf(xv, w2.x, a2.x); a2.y = fmaf(xv, w2.y, a2.y);
        a2.z = fmaf(xv, w2.z, a2.z); a2.w = fmaf(xv, w2.w, a2.w);
        a3.x = fmaf(xv, w3.x, a3.x); a3.y = fmaf(xv, w3.y, a3.y);
        a3.z = fmaf(xv, w3.z, a3.z); a3.w = fmaf(xv, w3.w, a3.w);
    }
    float4* P = (float4*)((isU ? g_P_u : g_P_i) + ((size_t)r * N + n) * 16);
    P[0] = a0; P[1] = a1; P[2] = a2; P[3] = a3;
}

// ---------------- kernel 1: per-edge ead (unchanged from R12) ----------------
__global__ __launch_bounds__(256) void phase1_kernel(
    const float* __restrict__ user_h,     const float* __restrict__ item_h,
    const float* __restrict__ user_hsum,  const float* __restrict__ item_hsum,
    const float* __restrict__ review_feat,
    const float* __restrict__ prototypes, const float* __restrict__ eta,
    const int*   __restrict__ rows,       const int*   __restrict__ cols)
{
    __shared__ float sm[256];
    const int r = blockIdx.y;
    if (threadIdx.x < 256) sm[threadIdx.x] = prototypes[threadIdx.x];
    __syncthreads();

    const int lane = threadIdx.x & 31;
    const int warp = threadIdx.x >> 5;
    const int e = blockIdx.x * 8 + warp;
    if (e >= E_N) return;

    const size_t idx = (size_t)r * E_N + e;
    const int row = rows[idx];
    const int col = cols[idx];
    const unsigned FULL = 0xffffffffu;

    const int dh = lane & 15;
    float hval;
    if (lane < 16) hval = __ldg(user_h + ((size_t)r * U_N + row) * 16 + dh);
    else           hval = __ldg(item_h + ((size_t)r * I_N + col) * 16 + dh);

    const float* uh = user_hsum + ((size_t)r * U_N + row) * 64;
    const float* ih = item_hsum + ((size_t)r * I_N + col) * 64;
    float4 hs;
    if (lane < 16) hs = *(const float4*)(uh + 4 * lane);
    else           hs = *(const float4*)(ih + 4 * (lane - 16));

    const float4* rf4 = (const float4*)(review_feat + idx * 256);
    float4 ra = __ldcs(rf4 + lane * 2);
    float4 rb = __ldcs(rf4 + lane * 2 + 1);

    const float etav = eta[idx];

    float othv = __shfl_xor_sync(FULL, hval, 16);
    float dot = red16(hval * othv);
    float ss = red16(hval * hval);
    float oss = __shfl_xor_sync(FULL, ss, 16);
    float sim_k = 2.0f * dot * rsqrtf(ss * oss);

    float4 o4;
    o4.x = __shfl_xor_sync(FULL, hs.x, 16);
    o4.y = __shfl_xor_sync(FULL, hs.y, 16);
    o4.z = __shfl_xor_sync(FULL, hs.z, 16);
    o4.w = __shfl_xor_sync(FULL, hs.w, 16);
    float p = hs.x * o4.x + hs.y * o4.y + hs.z * o4.z + hs.w * o4.w;
    p += __shfl_xor_sync(FULL, p, 1);
    p += __shfl_xor_sync(FULL, p, 2);
    float ek = __expf(2.0f * p);
    float Ssim = ek;
    Ssim += __shfl_xor_sync(FULL, Ssim, 4);
    Ssim += __shfl_xor_sync(FULL, Ssim, 8);
    float exp_sim = __expf(sim_k) / Ssim;

    const float4* pr4 = (const float4*)sm;
    float4 pa = pr4[lane * 2];
    float4 pb = pr4[lane * 2 + 1];
    float ad = ra.x * pa.x + ra.y * pa.y + ra.z * pa.z + ra.w * pa.w
             + rb.x * pb.x + rb.y * pb.y + rb.z * pb.z + rb.w * pb.w;
    ad += __shfl_xor_sync(FULL, ad, 1);
    ad += __shfl_xor_sync(FULL, ad, 2);
    ad += __shfl_xor_sync(FULL, ad, 4);
    float eab = __expf(2.0f * ad);
    float Sad = eab;
    Sad += __shfl_xor_sync(FULL, Sad, 8);
    Sad += __shfl_xor_sync(FULL, Sad, 16);
    float e2 = __shfl_sync(FULL, eab, 16);
    float ead = e2 / Sad;

    float g = 1.0f / (1.0f + __expf(-etav));
    ead = g * ead + (1.0f - g) * exp_sim;

    if (lane == 0) {
        g_ead[idx] = ead;
        atomicAdd(&g_norm_u[row], ead);
        atomicAdd(&g_norm_i[col], ead);
    }
}

// ---------------- fused kernel v4: zip-in-register staging ----------------
__global__ __launch_bounds__(256) void proj_scatter_kernel(
    const float* __restrict__ review_feat,
    const float* __restrict__ review_w_fwd, const float* __restrict__ review_w_rev,
    const int* __restrict__ rows, const int* __restrict__ cols,
    float* __restrict__ int_dist_out)
{
    __shared__ float      smW[64 * 36];
    __shared__ ulonglong2 smrf[32 * 33];
    __shared__ float      smw[PS_EDGES];
    __shared__ int2       smrc[PS_EDGES];
    float* smres = (float*)smrf;                    // overlay after GEMM

    const int r = blockIdx.y;
    const int tid = threadIdx.x;
    const int e0 = blockIdx.x * PS_EDGES;

    // ---- stage weights: smW[j*36 + o] ----
    for (int i = tid; i < 2048; i += 256) {
        int o = i & 31, j = i >> 5;
        float w = (o < 16) ? review_w_fwd[r * 1024 + j * 16 + o]
                           : review_w_rev[r * 1024 + j * 16 + (o - 16)];
        smW[j * 36 + o] = w;
    }

    // ---- stage rf_k: zip edge pairs in registers, store STS.128 ----
    // 512 tasks: p = pair (0..31), q = float4 chunk (0..15)
    for (int i = tid; i < 512; i += 256) {
        int p = i >> 4, q = i & 15;
        int ee = e0 + 2 * p;
        float4 v0 = {0,0,0,0}, v1 = {0,0,0,0};
        if (ee < E_N)
            v0 = __ldcs((const float4*)(review_feat + ((size_t)r * E_N + ee) * 256 + 128) + q);
        if (ee + 1 < E_N)
            v1 = __ldcs((const float4*)(review_feat + ((size_t)r * E_N + ee + 1) * 256 + 128) + q);
        ulonglong2 za, zb;
        za.x = pack2(v0.x, v1.x);   // j = 4q
        za.y = pack2(v0.y, v1.y);   // j = 4q+1
        zb.x = pack2(v0.z, v1.z);   // j = 4q+2
        zb.y = pack2(v0.w, v1.w);   // j = 4q+3
        smrf[p * 33 + q * 2]     = za;
        smrf[p * 33 + q * 2 + 1] = zb;
    }

    // ---- w-stage: one thread per edge ----
    if (tid < PS_EDGES) {
        int eg = e0 + tid;
        if (eg < E_N) {
            const size_t idx = (size_t)r * E_N + eg;
            const int row = rows[idx];
            const int col = cols[idx];
            const float ead = g_ead[idx];
            const float w = ead * rsqrtf(g_norm_u[row] * g_norm_i[col]);
            int_dist_out[idx] = w;
            smw[tid] = w;
            smrc[tid] = make_int2(row, col);
        }
    }
    __syncthreads();

    // ---- GEMM: warp owns 4 pairs x 32 outs; lane = (pair_local, o4) ----
    const int lane = tid & 31;
    const int warp = tid >> 5;
    const int p_local = lane >> 3;
    const int o4 = lane & 7;
    const int pair = warp * 4 + p_local;
    {
        unsigned long long acc2[4] = {0ull, 0ull, 0ull, 0ull};
        const ulonglong2* rfp = smrf + pair * 33;
        const float* wp = smW + o4 * 4;
#pragma unroll
        for (int jq = 0; jq < 16; jq++) {
            ulonglong2 rva = rfp[jq * 2];
            ulonglong2 rvb = rfp[jq * 2 + 1];
            float4 w0 = *(const float4*)(wp + (4*jq+0) * 36);
            float4 w1 = *(const float4*)(wp + (4*jq+1) * 36);
            float4 w2 = *(const float4*)(wp + (4*jq+2) * 36);
            float4 w3 = *(const float4*)(wp + (4*jq+3) * 36);
            acc2[0] = fma2(rva.x, dup2(w0.x), acc2[0]);
            acc2[1] = fma2(rva.x, dup2(w0.y), acc2[1]);
            acc2[2] = fma2(rva.x, dup2(w0.z), acc2[2]);
            acc2[3] = fma2(rva.x, dup2(w0.w), acc2[3]);
            acc2[0] = fma2(rva.y, dup2(w1.x), acc2[0]);
            acc2[1] = fma2(rva.y, dup2(w1.y), acc2[1]);
            acc2[2] = fma2(rva.y, dup2(w1.z), acc2[2]);
            acc2[3] = fma2(rva.y, dup2(w1.w), acc2[3]);
            acc2[0] = fma2(rvb.x, dup2(w2.x), acc2[0]);
            acc2[1] = fma2(rvb.x, dup2(w2.y), acc2[1]);
            acc2[2] = fma2(rvb.x, dup2(w2.z), acc2[2]);
            acc2[3] = fma2(rvb.x, dup2(w2.w), acc2[3]);
            acc2[0] = fma2(rvb.y, dup2(w3.x), acc2[0]);
            acc2[1] = fma2(rvb.y, dup2(w3.y), acc2[1]);
            acc2[2] = fma2(rvb.y, dup2(w3.z), acc2[2]);
            acc2[3] = fma2(rvb.y, dup2(w3.w), acc2[3]);
        }
        __syncthreads();

        const int el = pair * 2;
#pragma unroll
        for (int oo = 0; oo < 4; oo++) {
            float lo, hi;
            unpack2(acc2[oo], lo, hi);
            smres[el * 33 + o4 * 4 + oo] = lo;
            smres[(el + 1) * 33 + o4 * 4 + oo] = hi;
        }
    }
    __syncthreads();

    // ---- scatter: 64 edges x 8 threads ----
#pragma unroll
    for (int it = 0; it < 2; it++) {
        int item = tid + it * 256;
        int el = item >> 3;
        int q  = item & 7;
        int eg = e0 + el;
        if (eg >= E_N) continue;
        const float w = smw[el];
        const int2 rc = smrc[el];

        float4 p4;
        float* dest;
        const float* res = smres + el * 33;
        float m0, m1, m2, m3;
        if (q < 4) {
            m0 = res[q*4+0]; m1 = res[q*4+1]; m2 = res[q*4+2]; m3 = res[q*4+3];
            p4 = *(const float4*)(g_P_u + ((size_t)r * U_N + rc.x) * 16 + q * 4);
            dest = g_ifeat + rc.y * 16 + q * 4;
        } else {
            const int qq = q - 4;
            m0 = res[16+qq*4+0]; m1 = res[16+qq*4+1]; m2 = res[16+qq*4+2]; m3 = res[16+qq*4+3];
            p4 = *(const float4*)(g_P_i + ((size_t)r * I_N + rc.y) * 16 + qq * 4);
            dest = g_ufeat + rc.x * 16 + qq * 4;
        }
        float4 mv;
        mv.x = (m0 + p4.x) * w;
        mv.y = (m1 + p4.y) * w;
        mv.z = (m2 + p4.z) * w;
        mv.w = (m3 + p4.w) * w;
        red_v4(dest, mv);
    }
}

// ---------------- kernel 3: leaky + FC, float4-aligned x rows ----------------
#define NB_U ((U_N + 63) / 64)
#define NB_I ((I_N + 63) / 64)
__global__ __launch_bounds__(256) void fc_kernel(
    const float* __restrict__ ufc_w, const float* __restrict__ ufc_b,
    const float* __restrict__ ifc_w, const float* __restrict__ ifc_b,
    float* __restrict__ out)
{
    __shared__ float smx[64 * 20];     // stride 20 -> 16B-aligned rows
    const int tid = threadIdx.x;
    const bool isU = (blockIdx.x < NB_U);
    const int nb = (isU ? blockIdx.x : (blockIdx.x - NB_U)) * 64;
    const int N = isU ? U_N : I_N;
    const float* feat = isU ? g_ufeat : g_ifeat;
    const float* W = isU ? ufc_w : ifc_w;
    const float* B = isU ? ufc_b : ifc_b;
    float* outp = out + (isU ? 0 : (size_t)U_N * 64);

    for (int i = tid; i < 1024; i += 256) {
        int n = i >> 4, j = i & 15;
        int ng = nb + n;
        float x = (ng < N) ? feat[ng * 16 + j] : 0.f;
        x = (x >= 0.f) ? x : 0.1f * x;
        smx[n * 20 + j] = x;
    }
    __syncthreads();

    const int o = tid & 63;
    const int g = tid >> 6;
    float wr[16];
#pragma unroll
    for (int j = 0; j < 16; j++) wr[j] = W[j * 64 + o];
    const float b = B[o];

#pragma unroll
    for (int i = 0; i < 16; i++) {
        int n = g + i * 4;
        int ng = nb + n;
        if (ng < N) {
            float acc = b;
            const float4* xr = (const float4*)(smx + n * 20);
#pragma unroll
            for (int j4 = 0; j4 < 4; j4++) {
                float4 xq = xr[j4];
                acc = fmaf(xq.x, wr[j4*4+0], acc);
                acc = fmaf(xq.y, wr[j4*4+1], acc);
                acc = fmaf(xq.z, wr[j4*4+2], acc);
                acc = fmaf(xq.w, wr[j4*4+3], acc);
            }
            outp[(size_t)ng * 64 + o] = acc;
        }
    }
}

// ---------------- stream/event resources ----------------
static cudaStream_t g_side_stream = nullptr;
static cudaEvent_t  g_ev_fork = nullptr;
static cudaEvent_t  g_ev_join = nullptr;
namespace {
struct _StreamInit {
    _StreamInit() {
        cudaStreamCreateWithFlags(&g_side_stream, cudaStreamNonBlocking);
        cudaEventCreateWithFlags(&g_ev_fork, cudaEventDisableTiming);
        cudaEventCreateWithFlags(&g_ev_join, cudaEventDisableTiming);
    }
} _stream_init;
}

// ---------------- launch ----------------
extern "C" void kernel_launch(void* const* d_in, const int* in_sizes, int n_in,
                              void* d_out, int out_size)
{
    const float* user_h       = (const float*)d_in[0];
    const float* item_h       = (const float*)d_in[1];
    const float* user_hsum    = (const float*)d_in[2];
    const float* item_hsum    = (const float*)d_in[3];
    const float* review_feat  = (const float*)d_in[4];
    const float* prototypes   = (const float*)d_in[5];
    const float* eta          = (const float*)d_in[6];
    const float* node_w_fwd   = (const float*)d_in[7];
    const float* node_w_rev   = (const float*)d_in[8];
    const float* review_w_fwd = (const float*)d_in[9];
    const float* review_w_rev = (const float*)d_in[10];
    const float* ufc_w        = (const float*)d_in[11];
    const float* ufc_b        = (const float*)d_in[12];
    const float* ifc_w        = (const float*)d_in[13];
    const float* ifc_b        = (const float*)d_in[14];
    const int*   rows         = (const int*)d_in[15];
    const int*   cols         = (const int*)d_in[16];
    float* out = (float*)d_out;

    // fork: precompute on side stream, overlapping phase1
    cudaEventRecord(g_ev_fork, 0);
    cudaStreamWaitEvent(g_side_stream, g_ev_fork, 0);
    dim3 pgrid((U_N + 255) / 256, R_N, 2);
    precompute_kernel<<<pgrid, 256, 0, g_side_stream>>>(user_h, item_h,
                                                        node_w_fwd, node_w_rev);
    cudaEventRecord(g_ev_join, g_side_stream);

    zero_kernel<<<(U_N * D_N + 255) / 256, 256>>>();
    dim3 egrid(E_N / 8, R_N);
    phase1_kernel<<<egrid, 256>>>(user_h, item_h, user_hsum, item_hsum,
                                  review_feat, prototypes, eta, rows, cols);

    cudaStreamWaitEvent(0, g_ev_join, 0);
    dim3 bgrid((E_N + PS_EDGES - 1) / PS_EDGES, R_N);
    proj_scatter_kernel<<<bgrid, 256>>>(review_feat, review_w_fwd, review_w_rev,
                                        rows, cols,
                                        out + (size_t)(U_N + I_N) * OUT_N);

    fc_kernel<<<NB_U + NB_I, 256>>>(ufc_w, ufc_b, ifc_w, ifc_b, out);
}